// round 15
// baseline (speedup 1.0000x reference)
#include <cuda_runtime.h>
#include <cuda_bf16.h>
#include <math.h>
#include <stdint.h>

// ---------------- problem constants ----------------
#define BB 4
#define CIN 2048
#define IC 512
#define C8 64
#define NCLS 81
#define HH 64
#define WW 64
#define HW 4096
#define OHW (128*128)
#define K2C1 (3*CIN/2)
#define K2C2 (3*IC/2)
#define K2HW (3*HW/2)    // 6144

// ---------------- scratch ----------------
__device__ __align__(16) uint32_t g_wt1p[9*CIN*IC];
__device__ __align__(16) uint32_t g_wbc1[9*K2C1*IC];
__device__ __align__(16) uint32_t g_wt2p[9*IC*IC];
__device__ __align__(16) uint32_t g_wbc2[9*K2C2*IC];
__device__ __align__(16) uint32_t g_xtf[BB*CIN*HW];
__device__ __align__(16) uint32_t g_xsp[(size_t)BB*K2C1*HW];
__device__ __align__(16) uint32_t g_pamtf[BB*IC*HW];
__device__ __align__(16) uint32_t g_camsp[(size_t)BB*K2C2*HW];
__device__ __align__(16) uint32_t g_fbsp[BB*(3*C8/2)*HW];
__device__ __align__(16) uint32_t g_fcsp[BB*(3*C8/2)*HW];
__device__ __align__(16) uint32_t g_fdsp[(size_t)BB*IC*K2HW];
__device__ __align__(16) uint32_t g_attnsp[(size_t)BB*HW*K2HW];
__device__ __align__(16) uint32_t g_fp0cs[(size_t)BB*K2C2*HW];
__device__ __align__(16) uint32_t g_fc0cs[(size_t)BB*K2C2*HW];
__device__ __align__(16) uint32_t g_fc0rsA[(size_t)BB*IC*K2HW];
__device__ __align__(16) uint32_t g_fc0rsB[(size_t)BB*IC*K2HW];
__device__ __align__(16) uint32_t g_wdrs[IC*K2C2];
__device__ __align__(16) uint32_t g_wbcrs[128*K2C2];
__device__ __align__(16) uint32_t g_catsp[BB*IC*K2C2];
__device__ float g_campart[4*BB*IC*IC];
__device__ float g_wbc128[128*IC];
__device__ float g_bbc[128];
__device__ float g_fbc[BB*128*HW];
__device__ float g_featp0[BB*IC*HW];
__device__ float g_featc0[BB*IC*HW];
__device__ float g_fd[BB*IC*HW];
__device__ float g_attn[(size_t)BB*HW*HW];
__device__ float g_pam[BB*IC*HW];
__device__ float g_featp[BB*IC*HW];
__device__ float g_cam[BB*IC*HW];
__device__ float g_featc[BB*IC*HW];
__device__ float g_fusion[BB*IC*HW];
__device__ float g_pout[BB*NCLS*HW];
__device__ float g_cout[BB*NCLS*HW];
__device__ float g_fout[BB*NCLS*HW];

// ---------------- helpers ----------------
__device__ __forceinline__ uint32_t f2tf32(float f) {
    uint32_t r;
    asm("cvt.rna.tf32.f32 %0, %1;" : "=r"(r) : "f"(f));
    return r;
}
__device__ __forceinline__ void mma_tf32(float* c, const uint32_t* a, const uint32_t* b) {
    asm volatile(
        "mma.sync.aligned.m16n8k8.row.col.f32.tf32.tf32.f32 "
        "{%0,%1,%2,%3}, {%4,%5,%6,%7}, {%8,%9}, {%0,%1,%2,%3};"
        : "+f"(c[0]), "+f"(c[1]), "+f"(c[2]), "+f"(c[3])
        : "r"(a[0]), "r"(a[1]), "r"(a[2]), "r"(a[3]), "r"(b[0]), "r"(b[1]));
}
__device__ __forceinline__ void mma_bf16(float* c, const uint32_t* a, const uint32_t* b) {
    asm volatile(
        "mma.sync.aligned.m16n8k16.row.col.f32.bf16.bf16.f32 "
        "{%0,%1,%2,%3}, {%4,%5,%6,%7}, {%8,%9}, {%0,%1,%2,%3};"
        : "+f"(c[0]), "+f"(c[1]), "+f"(c[2]), "+f"(c[3])
        : "r"(a[0]), "r"(a[1]), "r"(a[2]), "r"(a[3]), "r"(b[0]), "r"(b[1]));
}
__device__ __forceinline__ void ldsm4(uint32_t& r0, uint32_t& r1, uint32_t& r2, uint32_t& r3,
                                      uint32_t addr) {
    asm volatile("ldmatrix.sync.aligned.m8n8.x4.shared.b16 {%0,%1,%2,%3}, [%4];"
                 : "=r"(r0), "=r"(r1), "=r"(r2), "=r"(r3) : "r"(addr));
}
__device__ __forceinline__ uint32_t bf16bits(float v) {
    __nv_bfloat16 b = __float2bfloat16_rn(v);
    return (uint32_t)*reinterpret_cast<unsigned short*>(&b);
}
__device__ __forceinline__ float bf16hi(float v) {
    return __bfloat162float(__float2bfloat16_rn(v));
}
__device__ __forceinline__ void split3(float v0, float v1, int phlo,
                                       uint32_t& u0, uint32_t& u1, uint32_t& u2) {
    uint32_t h0 = bf16bits(v0), h1 = bf16bits(v1);
    uint32_t l0 = bf16bits(v0 - bf16hi(v0)), l1 = bf16bits(v1 - bf16hi(v1));
    if (phlo == 1) { u0 = h0 | (l0 << 16); u1 = h0 | (h1 << 16); u2 = l1 | (h1 << 16); }
    else           { u0 = h0 | (h0 << 16); u1 = l0 | (h1 << 16); u2 = h1 | (l1 << 16); }
}
__device__ __forceinline__ void cp4u(uint32_t dst, const void* src) {
    asm volatile("cp.async.ca.shared.global [%0], [%1], 4;" :: "r"(dst), "l"(src));
}
__device__ __forceinline__ void cp16(uint32_t dst, const void* src) {
    asm volatile("cp.async.cg.shared.global [%0], [%1], 16;" :: "r"(dst), "l"(src));
}
__device__ __forceinline__ void cp16z(uint32_t dst, const void* src, uint32_t sz) {
    asm volatile("cp.async.cg.shared.global [%0], [%1], 16, %2;" :: "r"(dst), "l"(src), "r"(sz));
}
#define CP_COMMIT() asm volatile("cp.async.commit_group;")
#define CP_WAIT2()  asm volatile("cp.async.wait_group 2;")

// GEMM tile constants
#define CROW 12
#define CSTG (2*128*CROW)
#define GSMEM_BYTES (4*CSTG*4)

// conv smem: tf32 keeps k-major weight stages; bf16 uses ldmatrix A layout
#define WSTG_TF (16*136)
#define WSTG_BF (2*128*CROW)      // 2 k16 blocks x 128 rows x 12
#define ACTSTG (16*140)
#define CONV_SMEM_TF ((4*WSTG_TF + 2*ACTSTG)*4)   // 52736
#define CONV_SMEM_BF ((4*WSTG_BF + 2*ACTSTG)*4)   // 67072

// ---------------- conv weight prep: tf32, iter-major block16 k-major ----------------
__global__ void wtrans_kernel(const float* __restrict__ w, uint32_t* __restrict__ wt,
                              int Cin, int Cout) {
    size_t total = (size_t)Cout * Cin * 9;
    for (size_t i = (size_t)blockIdx.x * blockDim.x + threadIdx.x; i < total;
         i += (size_t)gridDim.x * blockDim.x) {
        int co = (int)(i % Cout);
        size_t r = i / Cout;
        int ci = (int)(r % Cin);
        int tap = (int)(r / Cin);
        size_t orow = ((size_t)((ci >> 4) * 9 + tap) << 4) + (ci & 15);
        wt[orow * Cout + co] = f2tf32(w[((size_t)co * Cin + ci) * 9 + tap]);
    }
}

// ---------------- conv weight prep: bf16 split3, ldmatrix A layout ----------------
// out[((kt*2 + blk)*Cout + co)*8 + j] where kt = (k2>>4)*9+tap, blk = (k2>>3)&1, j = k2&7
__global__ void wsplitbf_kernel(const float* __restrict__ w, uint32_t* __restrict__ wp,
                                int Cin, int Cout) {
    int K2Ct = 3 * Cin / 2;
    size_t total = (size_t)9 * K2Ct * Cout;
    for (size_t i = (size_t)blockIdx.x * blockDim.x + threadIdx.x; i < total;
         i += (size_t)gridDim.x * blockDim.x) {
        int co = (int)(i % Cout);
        size_t r = i / Cout;
        int k2 = (int)(r % K2Ct);
        int tap = (int)(r / K2Ct);
        uint32_t h[2];
#pragma unroll
        for (int j = 0; j < 2; j++) {
            int s = 2 * k2 + j;
            int ci = s / 3, part = s - 3 * ci;
            float v = w[((size_t)co * Cin + ci) * 9 + tap];
            if (part == 1) v = v - bf16hi(v);
            h[j] = bf16bits(v);
        }
        size_t kt = (size_t)(k2 >> 4) * 9 + tap;
        int blk = (k2 >> 3) & 1;
        int j = k2 & 7;
        wp[((kt * 2 + blk) * Cout + co) * 8 + j] = h[0] | (h[1] << 16);
    }
}

// ---------------- f32 -> tf32 bits ----------------
__global__ void packtf_kernel(const float* __restrict__ in, uint32_t* __restrict__ out,
                              size_t n) {
    for (size_t i = (size_t)blockIdx.x * blockDim.x + threadIdx.x; i < n;
         i += (size_t)gridDim.x * blockDim.x)
        out[i] = f2tf32(in[i]);
}

// ---------------- fused x pack: one read -> tf32 plane + split3 plane ----------------
__global__ void packx_kernel(const float* __restrict__ in, uint32_t* __restrict__ outsp,
                             uint32_t* __restrict__ outtf, int cshift, size_t total) {
    for (size_t i = (size_t)blockIdx.x * blockDim.x + threadIdx.x; i < total;
         i += (size_t)gridDim.x * blockDim.x) {
        size_t b = i >> (cshift + 12);
        int q = (int)((i >> 12) & ((1u << cshift) - 1));
        int pos = (int)(i & 4095);
        size_t base = (b << (cshift + 13)) + ((size_t)q << 13) + pos;
        float v0 = in[base];
        float v1 = in[base + 4096];
        uint32_t u0, u1, u2;
        split3(v0, v1, 2, u0, u1, u2);
        uint32_t* ob = outsp + b * ((size_t)3 << (cshift + 12));
        size_t rb = ((size_t)(3 * q)) << 12;
        ob[rb + pos] = u0;
        ob[rb + 4096 + pos] = u1;
        ob[rb + 8192 + pos] = u2;
        outtf[base] = f2tf32(v0);
        outtf[base + 4096] = f2tf32(v1);
    }
}

// ---------------- stack pwb|pwc + pbb|pbc ----------------
__global__ void stackwbc_kernel(const float* __restrict__ wb, const float* __restrict__ wc,
                                const float* __restrict__ bb, const float* __restrict__ bc,
                                float* __restrict__ wout, float* __restrict__ bout) {
    int i = blockIdx.x * 256 + threadIdx.x;
    if (i < 64 * IC) wout[i] = wb[i];
    else if (i < 128 * IC) wout[i] = wc[i - 64 * IC];
    if (i < 64) bout[i] = bb[i];
    else if (i < 128) bout[i] = bc[i - 64];
}

// ---------------- div-free channel-split pack ----------------
__global__ void packsp3_kernel(const float* __restrict__ in, uint32_t* __restrict__ out,
                               int cshift, size_t total, int phlo, int bshift = -1) {
    for (size_t i = (size_t)blockIdx.x * blockDim.x + threadIdx.x; i < total;
         i += (size_t)gridDim.x * blockDim.x) {
        size_t b = i >> (cshift + 12);
        int q = (int)((i >> 12) & ((1u << cshift) - 1));
        int pos = (int)(i & 4095);
        size_t bs = (bshift < 0) ? (b << (cshift + 13)) : (b << bshift);
        const float* xb = in + bs;
        float v0 = xb[((size_t)q << 13) + pos];
        float v1 = xb[((size_t)q << 13) + 4096 + pos];
        uint32_t u0, u1, u2;
        split3(v0, v1, phlo, u0, u1, u2);
        uint32_t* ob = out + b * ((size_t)3 << (cshift + 12));
        size_t rb = ((size_t)(3 * q)) << 12;
        ob[rb + pos] = u0;
        ob[rb + 4096 + pos] = u1;
        ob[rb + 8192 + pos] = u2;
    }
}

// ---------------- div-free row-split pack ----------------
__global__ void packrs3_kernel(const float* __restrict__ in, uint32_t* __restrict__ out,
                               size_t total, int kshift, int phlo) {
    for (size_t i = (size_t)blockIdx.x * blockDim.x + threadIdx.x; i < total;
         i += (size_t)gridDim.x * blockDim.x) {
        size_t r = i >> kshift;
        int g = (int)(i & ((1u << kshift) - 1));
        const float* row = in + (r << (kshift + 1));
        float2 v = *(const float2*)(row + 2 * g);
        uint32_t u0, u1, u2;
        split3(v.x, v.y, phlo, u0, u1, u2);
        uint32_t* o = out + r * ((size_t)3 << kshift) + 3 * (size_t)g;
        o[0] = u0; o[1] = u1; o[2] = u2;
    }
}

// ---------------- fused PAM softmax + row-split pack (B phases) ----------------
__global__ void softmax_pack_kernel(const float* __restrict__ logits,
                                    uint32_t* __restrict__ outsp) {
    size_t row = blockIdx.x;
    const float4* p4 = (const float4*)(logits + row * (size_t)HW);
    int t = threadIdx.x;
    __shared__ float red[256];
    __shared__ float srow[4096];
    float4 v[4];
    float m = -1e30f;
#pragma unroll
    for (int i = 0; i < 4; i++) {
        v[i] = p4[t + i * 256];
        m = fmaxf(m, fmaxf(fmaxf(v[i].x, v[i].y), fmaxf(v[i].z, v[i].w)));
    }
    red[t] = m;
    __syncthreads();
    for (int s = 128; s > 0; s >>= 1) {
        if (t < s) red[t] = fmaxf(red[t], red[t + s]);
        __syncthreads();
    }
    m = red[0];
    __syncthreads();
    float sum = 0.f;
#pragma unroll
    for (int i = 0; i < 4; i++) {
        float4 e;
        e.x = __expf(v[i].x - m); e.y = __expf(v[i].y - m);
        e.z = __expf(v[i].z - m); e.w = __expf(v[i].w - m);
        sum += e.x + e.y + e.z + e.w;
        *(float4*)&srow[(t + i * 256) * 4] = e;
    }
    red[t] = sum;
    __syncthreads();
    for (int s = 128; s > 0; s >>= 1) {
        if (t < s) red[t] += red[t + s];
        __syncthreads();
    }
    float inv = 1.f / red[0];
    uint32_t* orow = outsp + row * (size_t)K2HW;
#pragma unroll
    for (int j = 0; j < 8; j++) {
        float a0 = srow[16 * t + 2 * j] * inv;
        float a1 = srow[16 * t + 2 * j + 1] * inv;
        uint32_t u0, u1, u2;
        split3(a0, a1, 2, u0, u1, u2);
        int ob = 24 * t + 3 * j;
        orow[ob] = u0; orow[ob + 1] = u1; orow[ob + 2] = u2;
    }
}

// ---------------- fused CAM split-K reduce + softmax + pack (A phases) ----------------
__global__ void cam_softmax_pack_kernel(const float* __restrict__ logits,
                                        uint32_t* __restrict__ outsp,
                                        int nparts, long pstride) {
    int t = threadIdx.x;
    const float4* p4 = (const float4*)(logits + (size_t)blockIdx.x * IC);
    float4 v = p4[t];
    for (int c = 1; c < nparts; c++) {
        const float4* q4 = (const float4*)(logits + (size_t)c * pstride + (size_t)blockIdx.x * IC);
        float4 w = q4[t];
        v.x += w.x; v.y += w.y; v.z += w.z; v.w += w.w;
    }
    __shared__ float red[128];
    float m = fmaxf(fmaxf(v.x, v.y), fmaxf(v.z, v.w));
    red[t] = m;
    __syncthreads();
    for (int s = 64; s > 0; s >>= 1) {
        if (t < s) red[t] = fmaxf(red[t], red[t + s]);
        __syncthreads();
    }
    float m1 = red[0];
    __syncthreads();
    float mn = fminf(fminf(v.x, v.y), fminf(v.z, v.w));
    red[t] = mn;
    __syncthreads();
    for (int s = 64; s > 0; s >>= 1) {
        if (t < s) red[t] = fminf(red[t], red[t + s]);
        __syncthreads();
    }
    float m2 = m1 - red[0];
    __syncthreads();
    float4 e;
    e.x = __expf(m1 - v.x - m2);
    e.y = __expf(m1 - v.y - m2);
    e.z = __expf(m1 - v.z - m2);
    e.w = __expf(m1 - v.w - m2);
    red[t] = e.x + e.y + e.z + e.w;
    __syncthreads();
    for (int s = 64; s > 0; s >>= 1) {
        if (t < s) red[t] += red[t + s];
        __syncthreads();
    }
    float inv = 1.f / red[0];
    uint32_t* orow = outsp + (size_t)blockIdx.x * K2C2;
    uint32_t u0, u1, u2;
    split3(e.x * inv, e.y * inv, 1, u0, u1, u2);
    orow[6 * t] = u0; orow[6 * t + 1] = u1; orow[6 * t + 2] = u2;
    split3(e.z * inv, e.w * inv, 1, u0, u1, u2);
    orow[6 * t + 3] = u0; orow[6 * t + 4] = u1; orow[6 * t + 5] = u2;
}

// ---------------- conv3x3 tf32, halo-tile act reuse (tap-inner, 256 thr) ----------------
__global__ __launch_bounds__(256, 2)
void conv_tf32ca_kernel(const uint32_t* __restrict__ xtf, const uint32_t* __restrict__ wt,
                        float* __restrict__ out,
                        const float* __restrict__ s, const float* __restrict__ bias,
                        int Cin, int relu) {
    const int Cout = gridDim.y * 128;
    extern __shared__ uint32_t dyn[];
    int sb = blockIdx.x;
    int b = sb >> 5;
    int y0 = (sb & 31) * 2;
    int co0 = blockIdx.y * 128;
    int t = threadIdx.x;
    int lane = t & 31, wid = t >> 5;
    int wm = (wid & 3) * 32, wn = (wid >> 2) * 64;
    int lg = lane >> 2, lq = lane & 3;
    const uint32_t* xb = xtf + (size_t)b * Cin * HW;
    const int iters = (Cin / 16) * 9;
    uint32_t smb = (uint32_t)__cvta_generic_to_shared(dyn);
    uint32_t asmb = smb + 4 * WSTG_TF * 4;

    if (t < 128) {
        int buf = t >> 6, k = (t >> 2) & 15, c = t & 3;
        int hc = (c == 0) ? 3 : (c == 1) ? 68 : (c == 2) ? 71 : 136;
        dyn[4 * WSTG_TF + buf * ACTSTG + k * 140 + hc] = 0;
    }

    auto issue = [&](int kt) {
        if (kt < iters) {
            int st = kt & 3;
            uint32_t sW = smb + st * WSTG_TF * 4;
            int gk = kt * 16;
#pragma unroll
            for (int i = 0; i < 2; i++) {
                int f = t + i * 256;
                int row = f >> 5, c4 = (f & 31) * 4;
                cp16(sW + (uint32_t)(row * 136 + c4) * 4,
                     wt + (size_t)(gk + row) * Cout + co0 + c4);
            }
            if (kt % 3 == 0) {
                int a = kt / 3;
                int cb = a / 3;
                int dy = a - cb * 3 - 1;
                int k0g = cb * 16;
                uint32_t sAct = asmb + (a & 1) * ACTSTG * 4;
#pragma unroll
                for (int i = 0; i < 2; i++) {
                    int id = t + i * 256;
                    int k = id >> 5;
                    int sg = (id >> 4) & 1;
                    int j = id & 15;
                    int iy = y0 + sg + dy;
                    bool inb = ((unsigned)iy < 64u);
                    const uint32_t* src = xb + (size_t)(k0g + k) * HW +
                                          (inb ? iy * WW : 0) + 4 * j;
                    cp16z(sAct + (uint32_t)(k * 140 + 4 + 68 * sg + 4 * j) * 4,
                          src, inb ? 16u : 0u);
                }
            }
        }
        CP_COMMIT();
    };

    issue(0); issue(1); issue(2);

    float acc[2][8][4];
#pragma unroll
    for (int i = 0; i < 2; i++)
#pragma unroll
        for (int j = 0; j < 8; j++)
#pragma unroll
            for (int q = 0; q < 4; q++) acc[i][j][q] = 0.f;

    const int rseg = wn >> 6;
    for (int kt = 0; kt < iters; kt++) {
        CP_WAIT2();
        __syncthreads();
        int st = kt & 3;
        const uint32_t* sW = dyn + st * WSTG_TF;
        int a = kt / 3;
        int dx = kt - a * 3 - 1;
        const uint32_t* sAct = dyn + 4 * WSTG_TF + (a & 1) * ACTSTG;
        int coff = 4 + 68 * rseg + dx;
#pragma unroll
        for (int k0 = 0; k0 < 16; k0 += 8) {
            uint32_t af[2][4], bf[8][2];
#pragma unroll
            for (int mt = 0; mt < 2; mt++) {
                int m = wm + mt * 16;
                af[mt][0] = sW[(k0 + lq) * 136 + m + lg];
                af[mt][1] = sW[(k0 + lq) * 136 + m + 8 + lg];
                af[mt][2] = sW[(k0 + 4 + lq) * 136 + m + lg];
                af[mt][3] = sW[(k0 + 4 + lq) * 136 + m + 8 + lg];
            }
#pragma unroll
            for (int nt = 0; nt < 8; nt++) {
                bf[nt][0] = sAct[(k0 + lq) * 140 + coff + nt * 8 + lg];
                bf[nt][1] = sAct[(k0 + 4 + lq) * 140 + coff + nt * 8 + lg];
            }
#pragma unroll
            for (int mt = 0; mt < 2; mt++)
#pragma unroll
                for (int nt = 0; nt < 8; nt++)
                    mma_tf32(acc[mt][nt], af[mt], bf[nt]);
        }
        issue(kt + 3);
    }

#pragma unroll
    for (int mt = 0; mt < 2; mt++) {
        int r0 = co0 + wm + mt * 16 + lg;
        float s0 = s ? s[r0] : 1.f, s1 = s ? s[r0 + 8] : 1.f;
        float b0 = bias ? bias[r0] : 0.f, b1 = bias ? bias[r0 + 8] : 0.f;
#pragma unroll
        for (int nt = 0; nt < 8; nt++) {
            int col = wn + nt * 8 + lq * 2;
            int yy = y0 + (col >> 6), xx = col & 63;
            float v0 = acc[mt][nt][0] * s0 + b0, v1 = acc[mt][nt][1] * s0 + b0;
            float v2 = acc[mt][nt][2] * s1 + b1, v3 = acc[mt][nt][3] * s1 + b1;
            if (relu) { v0 = fmaxf(v0, 0.f); v1 = fmaxf(v1, 0.f);
                        v2 = fmaxf(v2, 0.f); v3 = fmaxf(v3, 0.f); }
            size_t o0 = (((size_t)b * Cout + r0) * HH + yy) * WW + xx;
            size_t o1 = (((size_t)b * Cout + r0 + 8) * HH + yy) * WW + xx;
            *(float2*)(out + o0) = make_float2(v0, v1);
            *(float2*)(out + o1) = make_float2(v2, v3);
        }
    }
}

// ---------------- conv3x3 bf16 triple-split, halo acts + ldmatrix A ----------------
__global__ __launch_bounds__(256, 2)
void conv_bf16ca_kernel(const uint32_t* __restrict__ xsp, const uint32_t* __restrict__ wp,
                        float* __restrict__ out,
                        const float* __restrict__ s, const float* __restrict__ bias,
                        int Cin, int relu) {
    const int Cout = gridDim.y * 128;
    const int K2Ct = 3 * Cin / 2;
    extern __shared__ uint32_t dyn[];
    int sb = blockIdx.x;
    int b = sb >> 5;
    int y0 = (sb & 31) * 2;
    int co0 = blockIdx.y * 128;
    int t = threadIdx.x;
    int lane = t & 31, wid = t >> 5;
    int wm = (wid & 3) * 32, wn = (wid >> 2) * 64;
    int lg = lane >> 2, lq = lane & 3;
    const uint32_t* xb = xsp + (size_t)b * K2Ct * HW;
    const int iters = (K2Ct / 16) * 9;
    uint32_t smb = (uint32_t)__cvta_generic_to_shared(dyn);
    uint32_t asmb = smb + 4 * WSTG_BF * 4;

    if (t < 128) {
        int buf = t >> 6, k = (t >> 2) & 15, c = t & 3;
        int hc = (c == 0) ? 3 : (c == 1) ? 68 : (c == 2) ? 71 : 136;
        dyn[4 * WSTG_BF + buf * ACTSTG + k * 140 + hc] = 0;
    }

    auto issue = [&](int kt) {
        if (kt < iters) {
            int st = kt & 3;
            uint32_t sW = smb + st * WSTG_BF * 4;
#pragma unroll
            for (int i = 0; i < 2; i++) {
                int f = t + i * 256;           // 0..511
                int blk = f >> 8;              // k16 block
                int r = (f >> 1) & 127;        // co row
                int h = f & 1;
                cp16(sW + (uint32_t)((blk * 128 + r) * CROW + h * 4) * 4,
                     wp + (((size_t)kt * 2 + blk) * Cout + co0 + r) * 8 + h * 4);
            }
            if (kt % 3 == 0) {
                int a = kt / 3;
                int cb = a / 3;
                int dy = a - cb * 3 - 1;
                int k0g = cb * 16;
                uint32_t sAct = asmb + (a & 1) * ACTSTG * 4;
#pragma unroll
                for (int i = 0; i < 2; i++) {
                    int id = t + i * 256;
                    int k = id >> 5;
                    int sg = (id >> 4) & 1;
                    int j = id & 15;
                    int iy = y0 + sg + dy;
                    bool inb = ((unsigned)iy < 64u);
                    const uint32_t* src = xb + (size_t)(k0g + k) * HW +
                                          (inb ? iy * WW : 0) + 4 * j;
                    cp16z(sAct + (uint32_t)(k * 140 + 4 + 68 * sg + 4 * j) * 4,
                          src, inb ? 16u : 0u);
                }
            }
        }
        CP_COMMIT();
    };

    issue(0); issue(1); issue(2);

    float acc[2][8][4];
#pragma unroll
    for (int i = 0; i < 2; i++)
#pragma unroll
        for (int j = 0; j < 8; j++)
#pragma unroll
            for (int q = 0; q < 4; q++) acc[i][j][q] = 0.f;

    const int rseg = wn >> 6;
    for (int kt = 0; kt < iters; kt++) {
        CP_WAIT2();
        __syncthreads();
        int st = kt & 3;
        uint32_t sWb = smb + st * WSTG_BF * 4;
        int a = kt / 3;
        int dx = kt - a * 3 - 1;
        const uint32_t* sAct = dyn + 4 * WSTG_BF + (a & 1) * ACTSTG;
        int coff = 4 + 68 * rseg + dx;
#pragma unroll
        for (int k0 = 0; k0 < 16; k0 += 8) {
            int blk = k0 >> 3;
            uint32_t base = sWb + (uint32_t)(blk * 128 * CROW) * 4;
            uint32_t af[2][4], bf[8][2];
#pragma unroll
            for (int mt = 0; mt < 2; mt++) {
                int row = wm + mt * 16 + (lane & 15);
                ldsm4(af[mt][0], af[mt][1], af[mt][2], af[mt][3],
                      base + (uint32_t)(row * CROW + (lane >> 4) * 4) * 4);
            }
#pragma unroll
            for (int nt = 0; nt < 8; nt++) {
                bf[nt][0] = sAct[(k0 + lq) * 140 + coff + nt * 8 + lg];
                bf[nt][1] = sAct[(k0 + 4 + lq) * 140 + coff + nt * 8 + lg];
            }
#pragma unroll
            for (int mt = 0; mt < 2; mt++)
#pragma unroll
                for (int nt = 0; nt < 8; nt++)
                    mma_bf16(acc[mt][nt], af[mt], bf[nt]);
        }
        issue(kt + 3);
    }

#pragma unroll
    for (int mt = 0; mt < 2; mt++) {
        int r0 = co0 + wm + mt * 16 + lg;
        float s0 = s ? s[r0] : 1.f, s1 = s ? s[r0 + 8] : 1.f;
        float b0 = bias ? bias[r0] : 0.f, b1 = bias ? bias[r0 + 8] : 0.f;
#pragma unroll
        for (int nt = 0; nt < 8; nt++) {
            int col = wn + nt * 8 + lq * 2;
            int yy = y0 + (col >> 6), xx = col & 63;
            float v0 = acc[mt][nt][0] * s0 + b0, v1 = acc[mt][nt][1] * s0 + b0;
            float v2 = acc[mt][nt][2] * s1 + b1, v3 = acc[mt][nt][3] * s1 + b1;
            if (relu) { v0 = fmaxf(v0, 0.f); v1 = fmaxf(v1, 0.f);
                        v2 = fmaxf(v2, 0.f); v3 = fmaxf(v3, 0.f); }
            size_t o0 = (((size_t)b * Cout + r0) * HH + yy) * WW + xx;
            size_t o1 = (((size_t)b * Cout + r0 + 8) * HH + yy) * WW + xx;
            *(float2*)(out + o0) = make_float2(v0, v1);
            *(float2*)(out + o1) = make_float2(v2, v3);
        }
    }
}

// ---------------- bf16-split3 GEMM (128 thr, 64x64 warp tiles, cp16 + ldmatrix) ----------------
template<int AT, int BT, int SWAP = 0>
__global__ __launch_bounds__(128, 3)
void gemm_bf16s2_kernel(const uint32_t* __restrict__ A, long aBS, int lda,
                        const uint32_t* __restrict__ B, long bBS, int ldb,
                        float* __restrict__ C, long cBS, int ldc,
                        const float* __restrict__ scalePtr,
                        const float* __restrict__ bias,
                        const float* __restrict__ Res,
                        int K2,
                        int zdiv = 1, long aKS = 0, long bKS = 0, long cKS = 0) {
    extern __shared__ uint32_t dyn[];
    int z = blockIdx.z;
    int zb = z / zdiv;
    int zc = z - zb * zdiv;
    const uint32_t* Ab = A + (size_t)zb * aBS + (size_t)zc * aKS;
    const uint32_t* Bb = B + (size_t)zb * bBS + (size_t)zc * bKS;
    float* Cb = C + (size_t)zb * cBS + (size_t)zc * cKS;
    const float* Rb = Res ? Res + (size_t)zb * cBS : (const float*)0;
    int n0 = (SWAP ? blockIdx.y : blockIdx.x) * 128;
    int m0 = (SWAP ? blockIdx.x : blockIdx.y) * 128;
    int t = threadIdx.x;
    int lane = t & 31, wid = t >> 5;
    int wm = (wid & 1) * 64, wn = (wid >> 1) * 64;
    int lg = lane >> 2, lq = lane & 3;
    const int iters = K2 / 8;
    uint32_t smb = (uint32_t)__cvta_generic_to_shared(dyn);

    auto issue = [&](int kt) {
        if (kt < iters) {
            int st = kt & 3;
            uint32_t sA = smb + st * CSTG * 4;
            uint32_t sB = sA + 128 * CROW * 4;
            int g0 = kt * 8;
            if (AT) {
                const uint32_t* ar = Ab + (size_t)(m0 + t) * lda + g0;
                cp16(sA + (uint32_t)(t * CROW) * 4, ar);
                cp16(sA + (uint32_t)(t * CROW + 4) * 4, ar + 4);
            } else {
#pragma unroll
                for (int i = 0; i < 8; i++) {
                    int f = t + i * 128;
                    int col = f & 127, r = f >> 7;
                    cp4u(sA + (uint32_t)(col * CROW + r) * 4,
                         Ab + (size_t)(g0 + r) * lda + m0 + col);
                }
            }
            if (BT) {
                const uint32_t* br = Bb + (size_t)(n0 + t) * ldb + g0;
                cp16(sB + (uint32_t)(t * CROW) * 4, br);
                cp16(sB + (uint32_t)(t * CROW + 4) * 4, br + 4);
            } else {
#pragma unroll
                for (int i = 0; i < 8; i++) {
                    int f = t + i * 128;
                    int col = f & 127, r = f >> 7;
                    cp4u(sB + (uint32_t)(col * CROW + r) * 4,
                         Bb + (size_t)(g0 + r) * ldb + n0 + col);
                }
            }
        }
        CP_COMMIT();
    };

    issue(0); issue(1); issue(2);

    float acc[4][8][4];
#pragma unroll
    for (int i = 0; i < 4; i++)
#pragma unroll
        for (int j = 0; j < 8; j++)
#pragma unroll
            for (int q = 0; q < 4; q++) acc[i][j][q] = 0.f;

    for (int kt = 0; kt < iters; kt++) {
        CP_WAIT2();
        __syncthreads();
        int st = kt & 3;
        uint32_t sA = smb + st * CSTG * 4;
        uint32_t sB = sA + 128 * CROW * 4;
        uint32_t af[4][4], bf[8][2];
#pragma unroll
        for (int mt = 0; mt < 4; mt++) {
            int row = wm + mt * 16 + (lane & 15);
            ldsm4(af[mt][0], af[mt][1], af[mt][2], af[mt][3],
                  sA + (uint32_t)(row * CROW + (lane >> 4) * 4) * 4);
        }
#pragma unroll
        for (int p = 0; p < 4; p++) {
            int row = wn + p * 16 + (lane & 7) + ((lane >> 4) & 1) * 8;
            ldsm4(bf[2 * p][0], bf[2 * p][1], bf[2 * p + 1][0], bf[2 * p + 1][1],
                  sB + (uint32_t)(row * CROW + ((lane >> 3) & 1) * 4) * 4);
        }
#pragma unroll
        for (int mt = 0; mt < 4; mt++)
#pragma unroll
            for (int nt = 0; nt < 8; nt++)
                mma_bf16(acc[mt][nt], af[mt], bf[nt]);
        issue(kt + 3);
    }

    float scale = scalePtr ? scalePtr[0] : 1.f;
#pragma unroll
    for (int mt = 0; mt < 4; mt++) {
        int r0 = m0 + wm + mt * 16 + lg;
        float bi0 = bias ? bias[r0] : 0.f;
        float bi1 = bias ? bias[r0 + 8] : 0.f;
#pragma unroll
        for (int nt = 0; nt < 8; nt++) {
            int col = n0 + wn + nt * 8 + lq * 2;
            size_t o0 = (size_t)r0 * ldc + col;
            size_t o1 = (size_t)(r0 + 8) * ldc + col;
            float v0 = acc[mt][nt][0], v1 = acc[mt][nt][1];
            float v2 = acc[mt][nt][2], v3 = acc[mt][nt][3];
            if (Rb) {
                v0 = scale * v0 + Rb[o0]; v1 = scale * v1 + Rb[o0 + 1];
                v2 = scale * v2 + Rb[o1]; v3 = scale * v3 + Rb[o1 + 1];
            } else {
                v0 += bi0; v1 += bi0; v2 += bi1; v3 += bi1;
            }
            *(float2*)(Cb + o0) = make_float2(v0, v1);
            *(float2*)(Cb + o1) = make_float2(v2, v3);
        }
    }
}

// ---------------- 3 output heads in one launch (SIMT, M=81) ----------------
struct Head3 {
    const float* A[3];
    const float* bias[3];
    const float* B[3];
    float* C[3];
};
__global__ void heads_kernel(Head3 h, int K) {
    int hd = blockIdx.y;
    const float* Ah = h.A[hd];
    const float* biash = h.bias[hd];
    const float* Bb = h.B[hd] + (size_t)blockIdx.z * K * HW;
    float* Cb = h.C[hd] + (size_t)blockIdx.z * NCLS * HW;
    int n0 = blockIdx.x * 128;
    int t = threadIdx.x, tx = t & 15, ty = t >> 4;
    __shared__ float aS[8][128];
    __shared__ float bS[8][128];
    float acc[8][8];
#pragma unroll
    for (int i = 0; i < 8; i++)
#pragma unroll
        for (int j = 0; j < 8; j++) acc[i][j] = 0.f;

    int mload = t >> 1;
    int kq = (t & 1) * 4;

    for (int ck = 0; ck < K; ck += 8) {
        float4 av = make_float4(0.f, 0.f, 0.f, 0.f);
        if (mload < NCLS)
            av = *(const float4*)(Ah + (size_t)mload * K + ck + kq);
        aS[kq+0][mload]=av.x; aS[kq+1][mload]=av.y; aS[kq+2][mload]=av.z; aS[kq+3][mload]=av.w;
#pragma unroll
        for (int i = 0; i < 4; ++i) {
            int idx = t + i * 256;
            int k = idx >> 7, n = idx & 127;
            bS[k][n] = Bb[(size_t)(ck + k) * HW + n0 + n];
        }
        __syncthreads();
#pragma unroll
        for (int kk = 0; kk < 8; ++kk) {
            float a[8], bv[8];
#pragma unroll
            for (int i = 0; i < 8; i++) a[i] = aS[kk][ty*8+i];
#pragma unroll
            for (int j = 0; j < 8; j++) bv[j] = bS[kk][tx*8+j];
#pragma unroll
            for (int i = 0; i < 8; i++)
#pragma unroll
                for (int j = 0; j < 8; j++) acc[i][j] = fmaf(a[i], bv[j], acc[i][j]);
        }
        __syncthreads();
    }

#pragma unroll
    for (int i = 0; i < 8; i++) {
        int m = ty * 8 + i;
        if (m < NCLS) {
            float bi = biash ? biash[m] : 0.f;
#pragma unroll
            for (int j = 0; j < 8; j++) {
                int n = n0 + tx * 8 + j;
                Cb[(size_t)m * HW + n] = acc[i][j] + bi;
            }
        }
    }
}

// ---------------- elementwise add ----------------
__global__ void add_kernel(const float* __restrict__ a, const float* __restrict__ b,
                           float* __restrict__ c, int n) {
    int i = blockIdx.x * 256 + threadIdx.x;
    if (i < n) c[i] = a[i] + b[i];
}

// ---------------- bilinear 2x upsample ----------------
__global__ void up2x_kernel(const float* __restrict__ src, float* __restrict__ dst) {
    int idx = blockIdx.x * 256 + threadIdx.x;
    const int total = BB * NCLS * OHW;
    if (idx >= total) return;
    int ox = idx & 127;
    int r = idx >> 7;
    int oy = r & 127;
    r >>= 7;
    float sy = oy * 0.5f - 0.25f;
    float sx = ox * 0.5f - 0.25f;
    float fy = floorf(sy), fx = floorf(sx);
    float wy = sy - fy, wx = sx - fx;
    int y0 = (int)fy, x0 = (int)fx;
    int y0c = max(y0, 0), y1c = min(y0 + 1, 63);
    int x0c = max(x0, 0), x1c = min(x0 + 1, 63);
    const float* s = src + (size_t)r * HW;
    float v00 = s[y0c*64+x0c], v01 = s[y0c*64+x1c];
    float v10 = s[y1c*64+x0c], v11 = s[y1c*64+x1c];
    dst[idx] = (1.f-wy)*((1.f-wx)*v00 + wx*v01) + wy*((1.f-wx)*v10 + wx*v11);
}

// ---------------- orchestration ----------------
extern "C" void kernel_launch(void* const* d_in, const int* in_sizes, int n_in,
                              void* d_out, int out_size) {
    (void)in_sizes; (void)n_in; (void)out_size;
    const float* x    = (const float*)d_in[0];
    const float* wp1  = (const float*)d_in[1];
    const float* sp1  = (const float*)d_in[2];
    const float* bp1  = (const float*)d_in[3];
    const float* wc1  = (const float*)d_in[4];
    const float* sc1  = (const float*)d_in[5];
    const float* bc1  = (const float*)d_in[6];
    const float* pwb  = (const float*)d_in[7];
    const float* pbb  = (const float*)d_in[8];
    const float* pwc  = (const float*)d_in[9];
    const float* pbc  = (const float*)d_in[10];
    const float* pwd  = (const float*)d_in[11];
    const float* pbd  = (const float*)d_in[12];
    const float* alpha = (const float*)d_in[13];
    const float* beta  = (const float*)d_in[14];
    const float* wp2  = (const float*)d_in[15];
    const float* sp2  = (const float*)d_in[16];
    const float* bp2  = (const float*)d_in[17];
    const float* wc2  = (const float*)d_in[18];
    const float* sc2  = (const float*)d_in[19];
    const float* bc2  = (const float*)d_in[20];
    const float* wlog = (const float*)d_in[21];
    const float* blog = (const float*)d_in[22];
    const float* wp3  = (const float*)d_in[23];
    const float* bp3  = (const float*)d_in[24];
    const float* wc3  = (const float*)d_in[25];
    const float* bc3  = (const float*)d_in[26];
    float* out = (float*)d_out;

    uint32_t *wt1p, *wbc1, *wt2p, *wbc2, *xtf, *xsp, *pamtf, *camsp;
    uint32_t *fbsp, *fcsp, *fdsp, *attnsp, *fp0cs, *fc0cs, *fc0rsA, *fc0rsB, *wdrs, *wbcrs, *catsp;
    float *campart, *wbc128, *bbc, *fbc;
    float *featp0, *featc0, *fd, *attn;
    float *pam, *featp, *cam, *featc, *fusion, *pout, *cout_, *fout;
    cudaGetSymbolAddress((void**)&wt1p, g_wt1p);
    cudaGetSymbolAddress((void**)&wbc1, g_wbc1);
    cudaGetSymbolAddress((void**)&wt2p, g_wt2p);
    cudaGetSymbolAddress((void**)&wbc2, g_wbc2);
    cudaGetSymbolAddress((void**)&xtf, g_xtf);
    cudaGetSymbolAddress((void**)&xsp, g_xsp);
    cudaGetSymbolAddress((void**)&pamtf, g_pamtf);
    cudaGetSymbolAddress((void**)&camsp, g_camsp);
    cudaGetSymbolAddress((void**)&fbsp, g_fbsp);
    cudaGetSymbolAddress((void**)&fcsp, g_fcsp);
    cudaGetSymbolAddress((void**)&fdsp, g_fdsp);
    cudaGetSymbolAddress((void**)&attnsp, g_attnsp);
    cudaGetSymbolAddress((void**)&fp0cs, g_fp0cs);
    cudaGetSymbolAddress((void**)&fc0cs, g_fc0cs);
    cudaGetSymbolAddress((void**)&fc0rsA, g_fc0rsA);
    cudaGetSymbolAddress((void**)&fc0rsB, g_fc0rsB);
    cudaGetSymbolAddress((void**)&wdrs, g_wdrs);
    cudaGetSymbolAddress((void**)&wbcrs, g_wbcrs);
    cudaGetSymbolAddress((void**)&catsp, g_catsp);
    cudaGetSymbolAddress((void**)&campart, g_campart);
    cudaGetSymbolAddress((void**)&wbc128, g_wbc128);
    cudaGetSymbolAddress((void**)&bbc, g_bbc);
    cudaGetSymbolAddress((void**)&fbc, g_fbc);
    cudaGetSymbolAddress((void**)&featp0, g_featp0);
    cudaGetSymbolAddress((void**)&featc0, g_featc0);
    cudaGetSymbolAddress((void**)&fd, g_fd);
    cudaGetSymbolAddress((void**)&attn, g_attn);
    cudaGetSymbolAddress((void**)&pam, g_pam);
    cudaGetSymbolAddress((void**)&featp, g_featp);
    cudaGetSymbolAddress((void**)&cam, g_cam);
    cudaGetSymbolAddress((void**)&featc, g_featc);
    cudaGetSymbolAddress((void**)&fusion, g_fusion);
    cudaGetSymbolAddress((void**)&pout, g_pout);
    cudaGetSymbolAddress((void**)&cout_, g_cout);
    cudaGetSymbolAddress((void**)&fout, g_fout);

    cudaFuncSetAttribute(conv_tf32ca_kernel,
                         cudaFuncAttributeMaxDynamicSharedMemorySize, CONV_SMEM_TF);
    cudaFuncSetAttribute(conv_bf16ca_kernel,
                         cudaFuncAttributeMaxDynamicSharedMemorySize, CONV_SMEM_BF);
    cudaFuncSetAttribute(gemm_bf16s2_kernel<0, 0>,
                         cudaFuncAttributeMaxDynamicSharedMemorySize, GSMEM_BYTES);
    cudaFuncSetAttribute(gemm_bf16s2_kernel<1, 0>,
                         cudaFuncAttributeMaxDynamicSharedMemorySize, GSMEM_BYTES);
    cudaFuncSetAttribute(gemm_bf16s2_kernel<1, 0, 1>,
                         cudaFuncAttributeMaxDynamicSharedMemorySize, GSMEM_BYTES);
    cudaFuncSetAttribute(gemm_bf16s2_kernel<1, 1>,
                         cudaFuncAttributeMaxDynamicSharedMemorySize, GSMEM_BYTES);
    cudaFuncSetAttribute(gemm_bf16s2_kernel<1, 1, 1>,
                         cudaFuncAttributeMaxDynamicSharedMemorySize, GSMEM_BYTES);

    // c1 path first so conv_bf16ca is launch #4 (ncu capture slot)
    wsplitbf_kernel<<<8192, 256>>>(wc1, wbc1, CIN, IC);                               // 1
    packx_kernel<<<16384, 256>>>(x, xsp, xtf, 10, (size_t)BB << 22);                  // 2
    wtrans_kernel<<<4096, 256>>>(wp1, wt1p, CIN, IC);                                 // 3
    conv_bf16ca_kernel<<<dim3(128, 4), 256, CONV_SMEM_BF>>>(xsp, wbc1, featc0, sc1, bc1, CIN, 1); // 4
    conv_tf32ca_kernel<<<dim3(128, 4), 256, CONV_SMEM_TF>>>(xtf, wt1p, featp0, sp1, bp1, CIN, 1);
    wtrans_kernel<<<2048, 256>>>(wp2, wt2p, IC, IC);
    wsplitbf_kernel<<<2048, 256>>>(wc2, wbc2, IC, IC);

    // PAM projections, all tensor: fb+fc merged (M=128) and fd, both on fp0cs
    stackwbc_kernel<<<256, 256>>>(pwb, pwc, pbb, pbc, wbc128, bbc);
    packsp3_kernel<<<8192, 256>>>(featp0, fp0cs, 8, (size_t)BB << 20, 2);
    packrs3_kernel<<<128, 256>>>(wbc128, wbcrs, (size_t)128 << 8, 8, 1);
    packrs3_kernel<<<512, 256>>>(pwd, wdrs, (size_t)IC << 8, 8, 1);
    gemm_bf16s2_kernel<1, 0, 1><<<dim3(1, 32, 4), 128, GSMEM_BYTES>>>(
        wbcrs, 0, K2C2,
        fp0cs, (long)K2C2 * HW, HW,
        fbc, (long)128 * HW, HW, 0, bbc, 0, K2C2);
    gemm_bf16s2_kernel<1, 0, 1><<<dim3(4, 32, 4), 128, GSMEM_BYTES>>>(
        wdrs, 0, K2C2,
        fp0cs, (long)K2C2 * HW, HW,
        fd, (long)IC * HW, HW, 0, pbd, 0, K2C2);

    // PAM logits + fused softmax+pack
    packsp3_kernel<<<1024, 256>>>(fbc, fbsp, 5, (size_t)BB << 17, 1, 19);
    packsp3_kernel<<<1024, 256>>>(fbc + 64 * HW, fcsp, 5, (size_t)BB << 17, 2, 19);
    gemm_bf16s2_kernel<0, 0><<<dim3(32, 32, 4), 128, GSMEM_BYTES>>>(
        fbsp, (long)(3 * C8 / 2) * HW, HW,
        fcsp, (long)(3 * C8 / 2) * HW, HW,
        attn, (long)HW * HW, HW, 0, 0, 0, 3 * C8 / 2);
    softmax_pack_kernel<<<BB * HW, 256>>>(attn, attnsp);

    // PAM apply (SWAP)
    packrs3_kernel<<<8192, 256>>>(fd, fdsp, (size_t)(BB * IC) << 11, 11, 1);
    gemm_bf16s2_kernel<1, 1, 1><<<dim3(4, 32, 4), 128, GSMEM_BYTES>>>(
        fdsp, (long)IC * K2HW, K2HW,
        attnsp, (long)HW * K2HW, K2HW,
        pam, (long)IC * HW, HW, alpha, 0, featp0, K2HW);

    // conv p2
    packtf_kernel<<<8192, 256>>>(pam, pamtf, (size_t)BB * IC * HW);
    conv_tf32ca_kernel<<<dim3(128, 4), 256, CONV_SMEM_TF>>>(pamtf, wt2p, featp, sp2, bp2, IC, 1);

    // CAM: gram split-K x4 + fused reduce/softmax/pack + apply (SWAP)
    packrs3_kernel<<<8192, 256>>>(featc0, fc0rsA, (size_t)(BB * IC) << 11, 11, 1);
    packrs3_kernel<<<8192, 256>>>(featc0, fc0rsB, (size_t)(BB * IC) << 11, 11, 2);
    gemm_bf16s2_kernel<1, 1><<<dim3(4, 4, 16), 128, GSMEM_BYTES>>>(
        fc0rsA, (long)IC * K2HW, K2HW,
        fc0rsB, (long)IC * K2HW, K2HW,
        campart, (long)IC * IC, IC, 0, 0, 0, K2HW / 4,
        4, (long)(K2HW / 4), (long)(K2HW / 4), (long)BB * IC * IC);
    cam_softmax_pack_kernel<<<BB * IC, 128>>>(campart, catsp, 4, (long)BB * IC * IC);
    packsp3_kernel<<<8192, 256>>>(featc0, fc0cs, 8, (size_t)BB << 20, 2);
    gemm_bf16s2_kernel<1, 0, 1><<<dim3(4, 32, 4), 128, GSMEM_BYTES>>>(
        catsp, (long)IC * K2C2, K2C2,
        fc0cs, (long)K2C2 * HW, HW,
        cam, (long)IC * HW, HW, beta, 0, featc0, K2C2);

    // conv c2
    packsp3_kernel<<<8192, 256>>>(cam, camsp, 8, (size_t)BB << 20, 2);
    conv_bf16ca_kernel<<<dim3(128, 4), 256, CONV_SMEM_BF>>>(camsp, wbc2, featc, sc2, bc2, IC, 1);

    // fusion + heads
    add_kernel<<<(BB * IC * HW) / 256, 256>>>(featp, featc, fusion, BB * IC * HW);
    Head3 h;
    h.A[0] = wp3;  h.bias[0] = bp3;  h.B[0] = featp;  h.C[0] = pout;
    h.A[1] = wc3;  h.bias[1] = bc3;  h.B[1] = featc;  h.C[1] = cout_;
    h.A[2] = wlog; h.bias[2] = blog; h.B[2] = fusion; h.C[2] = fout;
    heads_kernel<<<dim3(32, 3, 4), 256>>>(h, IC);

    // upsample 2x into output
    const int outElems = BB * NCLS * OHW;
    up2x_kernel<<<(outElems + 255) / 256, 256>>>(pout, out);
    up2x_kernel<<<(outElems + 255) / 256, 256>>>(cout_, out + outElems);
    up2x_kernel<<<(outElems + 255) / 256, 256>>>(fout, out + 2 * (size_t)outElems);
}

// round 16
// speedup vs baseline: 1.0184x; 1.0184x over previous
#include <cuda_runtime.h>
#include <cuda_bf16.h>
#include <math.h>
#include <stdint.h>

// ---------------- problem constants ----------------
#define BB 4
#define CIN 2048
#define IC 512
#define C8 64
#define NCLS 81
#define HH 64
#define WW 64
#define HW 4096
#define OHW (128*128)
#define K2C1 (3*CIN/2)
#define K2C2 (3*IC/2)
#define K2HW (3*HW/2)    // 6144

// ---------------- scratch ----------------
__device__ __align__(16) uint32_t g_wt1p[9*CIN*IC];
__device__ __align__(16) uint32_t g_wbc1[9*K2C1*IC];
__device__ __align__(16) uint32_t g_wt2p[9*IC*IC];
__device__ __align__(16) uint32_t g_wbc2[9*K2C2*IC];
__device__ __align__(16) uint32_t g_xtf[BB*CIN*HW];
__device__ __align__(16) uint32_t g_xsp[(size_t)BB*K2C1*HW];
__device__ __align__(16) uint32_t g_pamtf[BB*IC*HW];
__device__ __align__(16) uint32_t g_camsp[(size_t)BB*K2C2*HW];
__device__ __align__(16) uint32_t g_fbsp[BB*(3*C8/2)*HW];
__device__ __align__(16) uint32_t g_fcsp[BB*(3*C8/2)*HW];
__device__ __align__(16) uint32_t g_fdsp[(size_t)BB*IC*K2HW];
__device__ __align__(16) uint32_t g_attnsp[(size_t)BB*HW*K2HW];
__device__ __align__(16) uint32_t g_fp0cs[(size_t)BB*K2C2*HW];
__device__ __align__(16) uint32_t g_fc0cs[(size_t)BB*K2C2*HW];
__device__ __align__(16) uint32_t g_fc0rsA[(size_t)BB*IC*K2HW];
__device__ __align__(16) uint32_t g_fc0rsB[(size_t)BB*IC*K2HW];
__device__ __align__(16) uint32_t g_wdrs[IC*K2C2];
__device__ __align__(16) uint32_t g_wbcrs[128*K2C2];
__device__ __align__(16) uint32_t g_catsp[BB*IC*K2C2];
__device__ float g_campart[4*BB*IC*IC];
__device__ float g_wbc128[128*IC];
__device__ float g_bbc[128];
__device__ float g_fbc[BB*128*HW];
__device__ float g_featp0[BB*IC*HW];
__device__ float g_featc0[BB*IC*HW];
__device__ float g_fd[BB*IC*HW];
__device__ float g_attn[(size_t)BB*HW*HW];
__device__ float g_pam[BB*IC*HW];
__device__ float g_featp[BB*IC*HW];
__device__ float g_cam[BB*IC*HW];
__device__ float g_featc[BB*IC*HW];
__device__ float g_fusion[BB*IC*HW];
__device__ float g_pout[BB*NCLS*HW];
__device__ float g_cout[BB*NCLS*HW];
__device__ float g_fout[BB*NCLS*HW];

// ---------------- helpers ----------------
__device__ __forceinline__ uint32_t f2tf32(float f) {
    uint32_t r;
    asm("cvt.rna.tf32.f32 %0, %1;" : "=r"(r) : "f"(f));
    return r;
}
__device__ __forceinline__ void mma_tf32(float* c, const uint32_t* a, const uint32_t* b) {
    asm volatile(
        "mma.sync.aligned.m16n8k8.row.col.f32.tf32.tf32.f32 "
        "{%0,%1,%2,%3}, {%4,%5,%6,%7}, {%8,%9}, {%0,%1,%2,%3};"
        : "+f"(c[0]), "+f"(c[1]), "+f"(c[2]), "+f"(c[3])
        : "r"(a[0]), "r"(a[1]), "r"(a[2]), "r"(a[3]), "r"(b[0]), "r"(b[1]));
}
__device__ __forceinline__ void mma_bf16(float* c, const uint32_t* a, const uint32_t* b) {
    asm volatile(
        "mma.sync.aligned.m16n8k16.row.col.f32.bf16.bf16.f32 "
        "{%0,%1,%2,%3}, {%4,%5,%6,%7}, {%8,%9}, {%0,%1,%2,%3};"
        : "+f"(c[0]), "+f"(c[1]), "+f"(c[2]), "+f"(c[3])
        : "r"(a[0]), "r"(a[1]), "r"(a[2]), "r"(a[3]), "r"(b[0]), "r"(b[1]));
}
__device__ __forceinline__ void ldsm4(uint32_t& r0, uint32_t& r1, uint32_t& r2, uint32_t& r3,
                                      uint32_t addr) {
    asm volatile("ldmatrix.sync.aligned.m8n8.x4.shared.b16 {%0,%1,%2,%3}, [%4];"
                 : "=r"(r0), "=r"(r1), "=r"(r2), "=r"(r3) : "r"(addr));
}
__device__ __forceinline__ uint32_t bf16bits(float v) {
    __nv_bfloat16 b = __float2bfloat16_rn(v);
    return (uint32_t)*reinterpret_cast<unsigned short*>(&b);
}
__device__ __forceinline__ float bf16hi(float v) {
    return __bfloat162float(__float2bfloat16_rn(v));
}
__device__ __forceinline__ void split3(float v0, float v1, int phlo,
                                       uint32_t& u0, uint32_t& u1, uint32_t& u2) {
    uint32_t h0 = bf16bits(v0), h1 = bf16bits(v1);
    uint32_t l0 = bf16bits(v0 - bf16hi(v0)), l1 = bf16bits(v1 - bf16hi(v1));
    if (phlo == 1) { u0 = h0 | (l0 << 16); u1 = h0 | (h1 << 16); u2 = l1 | (h1 << 16); }
    else           { u0 = h0 | (h0 << 16); u1 = l0 | (h1 << 16); u2 = h1 | (l1 << 16); }
}
__device__ __forceinline__ void cp4u(uint32_t dst, const void* src) {
    asm volatile("cp.async.ca.shared.global [%0], [%1], 4;" :: "r"(dst), "l"(src));
}
__device__ __forceinline__ void cp16(uint32_t dst, const void* src) {
    asm volatile("cp.async.cg.shared.global [%0], [%1], 16;" :: "r"(dst), "l"(src));
}
__device__ __forceinline__ void cp16z(uint32_t dst, const void* src, uint32_t sz) {
    asm volatile("cp.async.cg.shared.global [%0], [%1], 16, %2;" :: "r"(dst), "l"(src), "r"(sz));
}
#define CP_COMMIT() asm volatile("cp.async.commit_group;")
#define CP_WAIT2()  asm volatile("cp.async.wait_group 2;")

// GEMM tile constants
#define CROW 12
#define CSTG (2*128*CROW)
#define GSMEM_BYTES (4*CSTG*4)

// conv smem: 4 weight stages (16x136 u32, k-major) + 2 act stages (16x140 u32)
#define WSTG (16*136)
#define ACTSTG (16*140)
#define CONV_SMEM ((4*WSTG + 2*ACTSTG)*4)   // 52736

// ---------------- conv weight prep: tf32, iter-major block16 k-major ----------------
__global__ void wtrans_kernel(const float* __restrict__ w, uint32_t* __restrict__ wt,
                              int Cin, int Cout) {
    size_t total = (size_t)Cout * Cin * 9;
    for (size_t i = (size_t)blockIdx.x * blockDim.x + threadIdx.x; i < total;
         i += (size_t)gridDim.x * blockDim.x) {
        int co = (int)(i % Cout);
        size_t r = i / Cout;
        int ci = (int)(r % Cin);
        int tap = (int)(r / Cin);
        size_t orow = ((size_t)((ci >> 4) * 9 + tap) << 4) + (ci & 15);
        wt[orow * Cout + co] = f2tf32(w[((size_t)co * Cin + ci) * 9 + tap]);
    }
}

// ---------------- conv weight prep: bf16 split3 pairs, iter-major block16 k-major ----------------
__global__ void wsplitbf_kernel(const float* __restrict__ w, uint32_t* __restrict__ wp,
                                int Cin, int Cout) {
    int K2Ct = 3 * Cin / 2;
    size_t total = (size_t)9 * K2Ct * Cout;
    for (size_t i = (size_t)blockIdx.x * blockDim.x + threadIdx.x; i < total;
         i += (size_t)gridDim.x * blockDim.x) {
        int co = (int)(i % Cout);
        size_t r = i / Cout;
        int k2 = (int)(r % K2Ct);
        int tap = (int)(r / K2Ct);
        uint32_t h[2];
#pragma unroll
        for (int j = 0; j < 2; j++) {
            int s = 2 * k2 + j;
            int ci = s / 3, part = s - 3 * ci;
            float v = w[((size_t)co * Cin + ci) * 9 + tap];
            if (part == 1) v = v - bf16hi(v);
            h[j] = bf16bits(v);
        }
        size_t orow = ((size_t)((k2 >> 4) * 9 + tap) << 4) + (k2 & 15);
        wp[orow * Cout + co] = h[0] | (h[1] << 16);
    }
}

// ---------------- f32 -> tf32 bits ----------------
__global__ void packtf_kernel(const float* __restrict__ in, uint32_t* __restrict__ out,
                              size_t n) {
    for (size_t i = (size_t)blockIdx.x * blockDim.x + threadIdx.x; i < n;
         i += (size_t)gridDim.x * blockDim.x)
        out[i] = f2tf32(in[i]);
}

// ---------------- fused x pack: one read -> tf32 plane + split3 plane ----------------
__global__ void packx_kernel(const float* __restrict__ in, uint32_t* __restrict__ outsp,
                             uint32_t* __restrict__ outtf, int cshift, size_t total) {
    for (size_t i = (size_t)blockIdx.x * blockDim.x + threadIdx.x; i < total;
         i += (size_t)gridDim.x * blockDim.x) {
        size_t b = i >> (cshift + 12);
        int q = (int)((i >> 12) & ((1u << cshift) - 1));
        int pos = (int)(i & 4095);
        size_t base = (b << (cshift + 13)) + ((size_t)q << 13) + pos;
        float v0 = in[base];
        float v1 = in[base + 4096];
        uint32_t u0, u1, u2;
        split3(v0, v1, 2, u0, u1, u2);
        uint32_t* ob = outsp + b * ((size_t)3 << (cshift + 12));
        size_t rb = ((size_t)(3 * q)) << 12;
        ob[rb + pos] = u0;
        ob[rb + 4096 + pos] = u1;
        ob[rb + 8192 + pos] = u2;
        outtf[base] = f2tf32(v0);
        outtf[base + 4096] = f2tf32(v1);
    }
}

// ---------------- stack pwb|pwc + pbb|pbc ----------------
__global__ void stackwbc_kernel(const float* __restrict__ wb, const float* __restrict__ wc,
                                const float* __restrict__ bb, const float* __restrict__ bc,
                                float* __restrict__ wout, float* __restrict__ bout) {
    int i = blockIdx.x * 256 + threadIdx.x;
    if (i < 64 * IC) wout[i] = wb[i];
    else if (i < 128 * IC) wout[i] = wc[i - 64 * IC];
    if (i < 64) bout[i] = bb[i];
    else if (i < 128) bout[i] = bc[i - 64];
}

// ---------------- div-free channel-split pack ----------------
__global__ void packsp3_kernel(const float* __restrict__ in, uint32_t* __restrict__ out,
                               int cshift, size_t total, int phlo, int bshift = -1) {
    for (size_t i = (size_t)blockIdx.x * blockDim.x + threadIdx.x; i < total;
         i += (size_t)gridDim.x * blockDim.x) {
        size_t b = i >> (cshift + 12);
        int q = (int)((i >> 12) & ((1u << cshift) - 1));
        int pos = (int)(i & 4095);
        size_t bs = (bshift < 0) ? (b << (cshift + 13)) : (b << bshift);
        const float* xb = in + bs;
        float v0 = xb[((size_t)q << 13) + pos];
        float v1 = xb[((size_t)q << 13) + 4096 + pos];
        uint32_t u0, u1, u2;
        split3(v0, v1, phlo, u0, u1, u2);
        uint32_t* ob = out + b * ((size_t)3 << (cshift + 12));
        size_t rb = ((size_t)(3 * q)) << 12;
        ob[rb + pos] = u0;
        ob[rb + 4096 + pos] = u1;
        ob[rb + 8192 + pos] = u2;
    }
}

// ---------------- div-free row-split pack ----------------
__global__ void packrs3_kernel(const float* __restrict__ in, uint32_t* __restrict__ out,
                               size_t total, int kshift, int phlo) {
    for (size_t i = (size_t)blockIdx.x * blockDim.x + threadIdx.x; i < total;
         i += (size_t)gridDim.x * blockDim.x) {
        size_t r = i >> kshift;
        int g = (int)(i & ((1u << kshift) - 1));
        const float* row = in + (r << (kshift + 1));
        float2 v = *(const float2*)(row + 2 * g);
        uint32_t u0, u1, u2;
        split3(v.x, v.y, phlo, u0, u1, u2);
        uint32_t* o = out + r * ((size_t)3 << kshift) + 3 * (size_t)g;
        o[0] = u0; o[1] = u1; o[2] = u2;
    }
}

// ---------------- fused PAM softmax + row-split pack (B phases) ----------------
__global__ void softmax_pack_kernel(const float* __restrict__ logits,
                                    uint32_t* __restrict__ outsp) {
    size_t row = blockIdx.x;
    const float4* p4 = (const float4*)(logits + row * (size_t)HW);
    int t = threadIdx.x;
    __shared__ float red[256];
    __shared__ float srow[4096];
    float4 v[4];
    float m = -1e30f;
#pragma unroll
    for (int i = 0; i < 4; i++) {
        v[i] = p4[t + i * 256];
        m = fmaxf(m, fmaxf(fmaxf(v[i].x, v[i].y), fmaxf(v[i].z, v[i].w)));
    }
    red[t] = m;
    __syncthreads();
    for (int s = 128; s > 0; s >>= 1) {
        if (t < s) red[t] = fmaxf(red[t], red[t + s]);
        __syncthreads();
    }
    m = red[0];
    __syncthreads();
    float sum = 0.f;
#pragma unroll
    for (int i = 0; i < 4; i++) {
        float4 e;
        e.x = __expf(v[i].x - m); e.y = __expf(v[i].y - m);
        e.z = __expf(v[i].z - m); e.w = __expf(v[i].w - m);
        sum += e.x + e.y + e.z + e.w;
        *(float4*)&srow[(t + i * 256) * 4] = e;
    }
    red[t] = sum;
    __syncthreads();
    for (int s = 128; s > 0; s >>= 1) {
        if (t < s) red[t] += red[t + s];
        __syncthreads();
    }
    float inv = 1.f / red[0];
    uint32_t* orow = outsp + row * (size_t)K2HW;
#pragma unroll
    for (int j = 0; j < 8; j++) {
        float a0 = srow[16 * t + 2 * j] * inv;
        float a1 = srow[16 * t + 2 * j + 1] * inv;
        uint32_t u0, u1, u2;
        split3(a0, a1, 2, u0, u1, u2);
        int ob = 24 * t + 3 * j;
        orow[ob] = u0; orow[ob + 1] = u1; orow[ob + 2] = u2;
    }
}

// ---------------- fused CAM split-K reduce + softmax + pack (A phases) ----------------
__global__ void cam_softmax_pack_kernel(const float* __restrict__ logits,
                                        uint32_t* __restrict__ outsp,
                                        int nparts, long pstride) {
    int t = threadIdx.x;
    const float4* p4 = (const float4*)(logits + (size_t)blockIdx.x * IC);
    float4 v = p4[t];
    for (int c = 1; c < nparts; c++) {
        const float4* q4 = (const float4*)(logits + (size_t)c * pstride + (size_t)blockIdx.x * IC);
        float4 w = q4[t];
        v.x += w.x; v.y += w.y; v.z += w.z; v.w += w.w;
    }
    __shared__ float red[128];
    float m = fmaxf(fmaxf(v.x, v.y), fmaxf(v.z, v.w));
    red[t] = m;
    __syncthreads();
    for (int s = 64; s > 0; s >>= 1) {
        if (t < s) red[t] = fmaxf(red[t], red[t + s]);
        __syncthreads();
    }
    float m1 = red[0];
    __syncthreads();
    float mn = fminf(fminf(v.x, v.y), fminf(v.z, v.w));
    red[t] = mn;
    __syncthreads();
    for (int s = 64; s > 0; s >>= 1) {
        if (t < s) red[t] = fminf(red[t], red[t + s]);
        __syncthreads();
    }
    float m2 = m1 - red[0];
    __syncthreads();
    float4 e;
    e.x = __expf(m1 - v.x - m2);
    e.y = __expf(m1 - v.y - m2);
    e.z = __expf(m1 - v.z - m2);
    e.w = __expf(m1 - v.w - m2);
    red[t] = e.x + e.y + e.z + e.w;
    __syncthreads();
    for (int s = 64; s > 0; s >>= 1) {
        if (t < s) red[t] += red[t + s];
        __syncthreads();
    }
    float inv = 1.f / red[0];
    uint32_t* orow = outsp + (size_t)blockIdx.x * K2C2;
    uint32_t u0, u1, u2;
    split3(e.x * inv, e.y * inv, 1, u0, u1, u2);
    orow[6 * t] = u0; orow[6 * t + 1] = u1; orow[6 * t + 2] = u2;
    split3(e.z * inv, e.w * inv, 1, u0, u1, u2);
    orow[6 * t + 3] = u0; orow[6 * t + 4] = u1; orow[6 * t + 5] = u2;
}

// ---------------- conv3x3 tf32, halo-tile act reuse (tap-inner, 256 thr) ----------------
__global__ __launch_bounds__(256, 2)
void conv_tf32ca_kernel(const uint32_t* __restrict__ xtf, const uint32_t* __restrict__ wt,
                        float* __restrict__ out,
                        const float* __restrict__ s, const float* __restrict__ bias,
                        int Cin, int relu) {
    const int Cout = gridDim.y * 128;
    extern __shared__ uint32_t dyn[];
    int sb = blockIdx.x;
    int b = sb >> 5;
    int y0 = (sb & 31) * 2;
    int co0 = blockIdx.y * 128;
    int t = threadIdx.x;
    int lane = t & 31, wid = t >> 5;
    int wm = (wid & 3) * 32, wn = (wid >> 2) * 64;
    int lg = lane >> 2, lq = lane & 3;
    const uint32_t* xb = xtf + (size_t)b * Cin * HW;
    const int iters = (Cin / 16) * 9;
    uint32_t smb = (uint32_t)__cvta_generic_to_shared(dyn);
    uint32_t asmb = smb + 4 * WSTG * 4;

    if (t < 128) {
        int buf = t >> 6, k = (t >> 2) & 15, c = t & 3;
        int hc = (c == 0) ? 3 : (c == 1) ? 68 : (c == 2) ? 71 : 136;
        dyn[4 * WSTG + buf * ACTSTG + k * 140 + hc] = 0;
    }

    auto issue = [&](int kt) {
        if (kt < iters) {
            int st = kt & 3;
            uint32_t sW = smb + st * WSTG * 4;
            int gk = kt * 16;
#pragma unroll
            for (int i = 0; i < 2; i++) {
                int f = t + i * 256;
                int row = f >> 5, c4 = (f & 31) * 4;
                cp16(sW + (uint32_t)(row * 136 + c4) * 4,
                     wt + (size_t)(gk + row) * Cout + co0 + c4);
            }
            if (kt % 3 == 0) {
                int a = kt / 3;
                int cb = a / 3;
                int dy = a - cb * 3 - 1;
                int k0g = cb * 16;
                uint32_t sAct = asmb + (a & 1) * ACTSTG * 4;
#pragma unroll
                for (int i = 0; i < 2; i++) {
                    int id = t + i * 256;
                    int k = id >> 5;
                    int sg = (id >> 4) & 1;
                    int j = id & 15;
                    int iy = y0 + sg + dy;
                    bool inb = ((unsigned)iy < 64u);
                    const uint32_t* src = xb + (size_t)(k0g + k) * HW +
                                          (inb ? iy * WW : 0) + 4 * j;
                    cp16z(sAct + (uint32_t)(k * 140 + 4 + 68 * sg + 4 * j) * 4,
                          src, inb ? 16u : 0u);
                }
            }
        }
        CP_COMMIT();
    };

    issue(0); issue(1); issue(2);

    float acc[2][8][4];
#pragma unroll
    for (int i = 0; i < 2; i++)
#pragma unroll
        for (int j = 0; j < 8; j++)
#pragma unroll
            for (int q = 0; q < 4; q++) acc[i][j][q] = 0.f;

    const int rseg = wn >> 6;
    for (int kt = 0; kt < iters; kt++) {
        CP_WAIT2();
        __syncthreads();
        int st = kt & 3;
        const uint32_t* sW = dyn + st * WSTG;
        int a = kt / 3;
        int dx = kt - a * 3 - 1;
        const uint32_t* sAct = dyn + 4 * WSTG + (a & 1) * ACTSTG;
        int coff = 4 + 68 * rseg + dx;
#pragma unroll
        for (int k0 = 0; k0 < 16; k0 += 8) {
            uint32_t af[2][4], bf[8][2];
#pragma unroll
            for (int mt = 0; mt < 2; mt++) {
                int m = wm + mt * 16;
                af[mt][0] = sW[(k0 + lq) * 136 + m + lg];
                af[mt][1] = sW[(k0 + lq) * 136 + m + 8 + lg];
                af[mt][2] = sW[(k0 + 4 + lq) * 136 + m + lg];
                af[mt][3] = sW[(k0 + 4 + lq) * 136 + m + 8 + lg];
            }
#pragma unroll
            for (int nt = 0; nt < 8; nt++) {
                bf[nt][0] = sAct[(k0 + lq) * 140 + coff + nt * 8 + lg];
                bf[nt][1] = sAct[(k0 + 4 + lq) * 140 + coff + nt * 8 + lg];
            }
#pragma unroll
            for (int mt = 0; mt < 2; mt++)
#pragma unroll
                for (int nt = 0; nt < 8; nt++)
                    mma_tf32(acc[mt][nt], af[mt], bf[nt]);
        }
        issue(kt + 3);
    }

#pragma unroll
    for (int mt = 0; mt < 2; mt++) {
        int r0 = co0 + wm + mt * 16 + lg;
        float s0 = s ? s[r0] : 1.f, s1 = s ? s[r0 + 8] : 1.f;
        float b0 = bias ? bias[r0] : 0.f, b1 = bias ? bias[r0 + 8] : 0.f;
#pragma unroll
        for (int nt = 0; nt < 8; nt++) {
            int col = wn + nt * 8 + lq * 2;
            int yy = y0 + (col >> 6), xx = col & 63;
            float v0 = acc[mt][nt][0] * s0 + b0, v1 = acc[mt][nt][1] * s0 + b0;
            float v2 = acc[mt][nt][2] * s1 + b1, v3 = acc[mt][nt][3] * s1 + b1;
            if (relu) { v0 = fmaxf(v0, 0.f); v1 = fmaxf(v1, 0.f);
                        v2 = fmaxf(v2, 0.f); v3 = fmaxf(v3, 0.f); }
            size_t o0 = (((size_t)b * Cout + r0) * HH + yy) * WW + xx;
            size_t o1 = (((size_t)b * Cout + r0 + 8) * HH + yy) * WW + xx;
            *(float2*)(out + o0) = make_float2(v0, v1);
            *(float2*)(out + o1) = make_float2(v2, v3);
        }
    }
}

// ---------------- conv3x3 bf16 triple-split, halo-tile act reuse (R14 form) ----------------
__global__ __launch_bounds__(256, 2)
void conv_bf16ca_kernel(const uint32_t* __restrict__ xsp, const uint32_t* __restrict__ wp,
                        float* __restrict__ out,
                        const float* __restrict__ s, const float* __restrict__ bias,
                        int Cin, int relu) {
    const int Cout = gridDim.y * 128;
    const int K2Ct = 3 * Cin / 2;
    extern __shared__ uint32_t dyn[];
    int sb = blockIdx.x;
    int b = sb >> 5;
    int y0 = (sb & 31) * 2;
    int co0 = blockIdx.y * 128;
    int t = threadIdx.x;
    int lane = t & 31, wid = t >> 5;
    int wm = (wid & 3) * 32, wn = (wid >> 2) * 64;
    int lg = lane >> 2, lq = lane & 3;
    const uint32_t* xb = xsp + (size_t)b * K2Ct * HW;
    const int iters = (K2Ct / 16) * 9;
    uint32_t smb = (uint32_t)__cvta_generic_to_shared(dyn);
    uint32_t asmb = smb + 4 * WSTG * 4;

    if (t < 128) {
        int buf = t >> 6, k = (t >> 2) & 15, c = t & 3;
        int hc = (c == 0) ? 3 : (c == 1) ? 68 : (c == 2) ? 71 : 136;
        dyn[4 * WSTG + buf * ACTSTG + k * 140 + hc] = 0;
    }

    auto issue = [&](int kt) {
        if (kt < iters) {
            int st = kt & 3;
            uint32_t sW = smb + st * WSTG * 4;
            int gk = kt * 16;
#pragma unroll
            for (int i = 0; i < 2; i++) {
                int f = t + i * 256;
                int row = f >> 5, c4 = (f & 31) * 4;
                cp16(sW + (uint32_t)(row * 136 + c4) * 4,
                     wp + (size_t)(gk + row) * Cout + co0 + c4);
            }
            if (kt % 3 == 0) {
                int a = kt / 3;
                int cb = a / 3;
                int dy = a - cb * 3 - 1;
                int k0g = cb * 16;
                uint32_t sAct = asmb + (a & 1) * ACTSTG * 4;
#pragma unroll
                for (int i = 0; i < 2; i++) {
                    int id = t + i * 256;
                    int k = id >> 5;
                    int sg = (id >> 4) & 1;
                    int j = id & 15;
                    int iy = y0 + sg + dy;
                    bool inb = ((unsigned)iy < 64u);
                    const uint32_t* src = xb + (size_t)(k0g + k) * HW +
                                          (inb ? iy * WW : 0) + 4 * j;
                    cp16z(sAct + (uint32_t)(k * 140 + 4 + 68 * sg + 4 * j) * 4,
                          src, inb ? 16u : 0u);
                }
            }
        }
        CP_COMMIT();
    };

    issue(0); issue(1); issue(2);

    float acc[2][8][4];
#pragma unroll
    for (int i = 0; i < 2; i++)
#pragma unroll
        for (int j = 0; j < 8; j++)
#pragma unroll
            for (int q = 0; q < 4; q++) acc[i][j][q] = 0.f;

    const int rseg = wn >> 6;
    for (int kt = 0; kt < iters; kt++) {
        CP_WAIT2();
        __syncthreads();
        int st = kt & 3;
        const uint32_t* sW = dyn + st * WSTG;
        int a = kt / 3;
        int dx = kt - a * 3 - 1;
        const uint32_t* sAct = dyn + 4 * WSTG + (a & 1) * ACTSTG;
        int coff = 4 + 68 * rseg + dx;
#pragma unroll
        for (int k0 = 0; k0 < 16; k0 += 8) {
            uint32_t af[2][4], bf[8][2];
#pragma unroll
            for (int mt = 0; mt < 2; mt++) {
                int m = wm + mt * 16;
                af[mt][0] = sW[(k0 + lq) * 136 + m + lg];
                af[mt][1] = sW[(k0 + lq) * 136 + m + 8 + lg];
                af[mt][2] = sW[(k0 + 4 + lq) * 136 + m + lg];
                af[mt][3] = sW[(k0 + 4 + lq) * 136 + m + 8 + lg];
            }
#pragma unroll
            for (int nt = 0; nt < 8; nt++) {
                bf[nt][0] = sAct[(k0 + lq) * 140 + coff + nt * 8 + lg];
                bf[nt][1] = sAct[(k0 + 4 + lq) * 140 + coff + nt * 8 + lg];
            }
#pragma unroll
            for (int mt = 0; mt < 2; mt++)
#pragma unroll
                for (int nt = 0; nt < 8; nt++)
                    mma_bf16(acc[mt][nt], af[mt], bf[nt]);
        }
        issue(kt + 3);
    }

#pragma unroll
    for (int mt = 0; mt < 2; mt++) {
        int r0 = co0 + wm + mt * 16 + lg;
        float s0 = s ? s[r0] : 1.f, s1 = s ? s[r0 + 8] : 1.f;
        float b0 = bias ? bias[r0] : 0.f, b1 = bias ? bias[r0 + 8] : 0.f;
#pragma unroll
        for (int nt = 0; nt < 8; nt++) {
            int col = wn + nt * 8 + lq * 2;
            int yy = y0 + (col >> 6), xx = col & 63;
            float v0 = acc[mt][nt][0] * s0 + b0, v1 = acc[mt][nt][1] * s0 + b0;
            float v2 = acc[mt][nt][2] * s1 + b1, v3 = acc[mt][nt][3] * s1 + b1;
            if (relu) { v0 = fmaxf(v0, 0.f); v1 = fmaxf(v1, 0.f);
                        v2 = fmaxf(v2, 0.f); v3 = fmaxf(v3, 0.f); }
            size_t o0 = (((size_t)b * Cout + r0) * HH + yy) * WW + xx;
            size_t o1 = (((size_t)b * Cout + r0 + 8) * HH + yy) * WW + xx;
            *(float2*)(out + o0) = make_float2(v0, v1);
            *(float2*)(out + o1) = make_float2(v2, v3);
        }
    }
}

// ---------------- bf16-split3 GEMM (128 thr, 64x64 warp tiles, cp16 + ldmatrix) ----------------
template<int AT, int BT, int SWAP = 0>
__global__ __launch_bounds__(128, 3)
void gemm_bf16s2_kernel(const uint32_t* __restrict__ A, long aBS, int lda,
                        const uint32_t* __restrict__ B, long bBS, int ldb,
                        float* __restrict__ C, long cBS, int ldc,
                        const float* __restrict__ scalePtr,
                        const float* __restrict__ bias,
                        const float* __restrict__ Res,
                        int K2,
                        int zdiv = 1, long aKS = 0, long bKS = 0, long cKS = 0) {
    extern __shared__ uint32_t dyn[];
    int z = blockIdx.z;
    int zb = z / zdiv;
    int zc = z - zb * zdiv;
    const uint32_t* Ab = A + (size_t)zb * aBS + (size_t)zc * aKS;
    const uint32_t* Bb = B + (size_t)zb * bBS + (size_t)zc * bKS;
    float* Cb = C + (size_t)zb * cBS + (size_t)zc * cKS;
    const float* Rb = Res ? Res + (size_t)zb * cBS : (const float*)0;
    int n0 = (SWAP ? blockIdx.y : blockIdx.x) * 128;
    int m0 = (SWAP ? blockIdx.x : blockIdx.y) * 128;
    int t = threadIdx.x;
    int lane = t & 31, wid = t >> 5;
    int wm = (wid & 1) * 64, wn = (wid >> 1) * 64;
    int lg = lane >> 2, lq = lane & 3;
    const int iters = K2 / 8;
    uint32_t smb = (uint32_t)__cvta_generic_to_shared(dyn);

    auto issue = [&](int kt) {
        if (kt < iters) {
            int st = kt & 3;
            uint32_t sA = smb + st * CSTG * 4;
            uint32_t sB = sA + 128 * CROW * 4;
            int g0 = kt * 8;
            if (AT) {
                const uint32_t* ar = Ab + (size_t)(m0 + t) * lda + g0;
                cp16(sA + (uint32_t)(t * CROW) * 4, ar);
                cp16(sA + (uint32_t)(t * CROW + 4) * 4, ar + 4);
            } else {
#pragma unroll
                for (int i = 0; i < 8; i++) {
                    int f = t + i * 128;
                    int col = f & 127, r = f >> 7;
                    cp4u(sA + (uint32_t)(col * CROW + r) * 4,
                         Ab + (size_t)(g0 + r) * lda + m0 + col);
                }
            }
            if (BT) {
                const uint32_t* br = Bb + (size_t)(n0 + t) * ldb + g0;
                cp16(sB + (uint32_t)(t * CROW) * 4, br);
                cp16(sB + (uint32_t)(t * CROW + 4) * 4, br + 4);
            } else {
#pragma unroll
                for (int i = 0; i < 8; i++) {
                    int f = t + i * 128;
                    int col = f & 127, r = f >> 7;
                    cp4u(sB + (uint32_t)(col * CROW + r) * 4,
                         Bb + (size_t)(g0 + r) * ldb + n0 + col);
                }
            }
        }
        CP_COMMIT();
    };

    issue(0); issue(1); issue(2);

    float acc[4][8][4];
#pragma unroll
    for (int i = 0; i < 4; i++)
#pragma unroll
        for (int j = 0; j < 8; j++)
#pragma unroll
            for (int q = 0; q < 4; q++) acc[i][j][q] = 0.f;

    for (int kt = 0; kt < iters; kt++) {
        CP_WAIT2();
        __syncthreads();
        int st = kt & 3;
        uint32_t sA = smb + st * CSTG * 4;
        uint32_t sB = sA + 128 * CROW * 4;
        uint32_t af[4][4], bf[8][2];
#pragma unroll
        for (int mt = 0; mt < 4; mt++) {
            int row = wm + mt * 16 + (lane & 15);
            ldsm4(af[mt][0], af[mt][1], af[mt][2], af[mt][3],
                  sA + (uint32_t)(row * CROW + (lane >> 4) * 4) * 4);
        }
#pragma unroll
        for (int p = 0; p < 4; p++) {
            int row = wn + p * 16 + (lane & 7) + ((lane >> 4) & 1) * 8;
            ldsm4(bf[2 * p][0], bf[2 * p][1], bf[2 * p + 1][0], bf[2 * p + 1][1],
                  sB + (uint32_t)(row * CROW + ((lane >> 3) & 1) * 4) * 4);
        }
#pragma unroll
        for (int mt = 0; mt < 4; mt++)
#pragma unroll
            for (int nt = 0; nt < 8; nt++)
                mma_bf16(acc[mt][nt], af[mt], bf[nt]);
        issue(kt + 3);
    }

    float scale = scalePtr ? scalePtr[0] : 1.f;
#pragma unroll
    for (int mt = 0; mt < 4; mt++) {
        int r0 = m0 + wm + mt * 16 + lg;
        float bi0 = bias ? bias[r0] : 0.f;
        float bi1 = bias ? bias[r0 + 8] : 0.f;
#pragma unroll
        for (int nt = 0; nt < 8; nt++) {
            int col = n0 + wn + nt * 8 + lq * 2;
            size_t o0 = (size_t)r0 * ldc + col;
            size_t o1 = (size_t)(r0 + 8) * ldc + col;
            float v0 = acc[mt][nt][0], v1 = acc[mt][nt][1];
            float v2 = acc[mt][nt][2], v3 = acc[mt][nt][3];
            if (Rb) {
                v0 = scale * v0 + Rb[o0]; v1 = scale * v1 + Rb[o0 + 1];
                v2 = scale * v2 + Rb[o1]; v3 = scale * v3 + Rb[o1 + 1];
            } else {
                v0 += bi0; v1 += bi0; v2 += bi1; v3 += bi1;
            }
            *(float2*)(Cb + o0) = make_float2(v0, v1);
            *(float2*)(Cb + o1) = make_float2(v2, v3);
        }
    }
}

// ---------------- 3 output heads in one launch (SIMT, M=81) ----------------
struct Head3 {
    const float* A[3];
    const float* bias[3];
    const float* B[3];
    float* C[3];
};
__global__ void heads_kernel(Head3 h, int K) {
    int hd = blockIdx.y;
    const float* Ah = h.A[hd];
    const float* biash = h.bias[hd];
    const float* Bb = h.B[hd] + (size_t)blockIdx.z * K * HW;
    float* Cb = h.C[hd] + (size_t)blockIdx.z * NCLS * HW;
    int n0 = blockIdx.x * 128;
    int t = threadIdx.x, tx = t & 15, ty = t >> 4;
    __shared__ float aS[8][128];
    __shared__ float bS[8][128];
    float acc[8][8];
#pragma unroll
    for (int i = 0; i < 8; i++)
#pragma unroll
        for (int j = 0; j < 8; j++) acc[i][j] = 0.f;

    int mload = t >> 1;
    int kq = (t & 1) * 4;

    for (int ck = 0; ck < K; ck += 8) {
        float4 av = make_float4(0.f, 0.f, 0.f, 0.f);
        if (mload < NCLS)
            av = *(const float4*)(Ah + (size_t)mload * K + ck + kq);
        aS[kq+0][mload]=av.x; aS[kq+1][mload]=av.y; aS[kq+2][mload]=av.z; aS[kq+3][mload]=av.w;
#pragma unroll
        for (int i = 0; i < 4; ++i) {
            int idx = t + i * 256;
            int k = idx >> 7, n = idx & 127;
            bS[k][n] = Bb[(size_t)(ck + k) * HW + n0 + n];
        }
        __syncthreads();
#pragma unroll
        for (int kk = 0; kk < 8; ++kk) {
            float a[8], bv[8];
#pragma unroll
            for (int i = 0; i < 8; i++) a[i] = aS[kk][ty*8+i];
#pragma unroll
            for (int j = 0; j < 8; j++) bv[j] = bS[kk][tx*8+j];
#pragma unroll
            for (int i = 0; i < 8; i++)
#pragma unroll
                for (int j = 0; j < 8; j++) acc[i][j] = fmaf(a[i], bv[j], acc[i][j]);
        }
        __syncthreads();
    }

#pragma unroll
    for (int i = 0; i < 8; i++) {
        int m = ty * 8 + i;
        if (m < NCLS) {
            float bi = biash ? biash[m] : 0.f;
#pragma unroll
            for (int j = 0; j < 8; j++) {
                int n = n0 + tx * 8 + j;
                Cb[(size_t)m * HW + n] = acc[i][j] + bi;
            }
        }
    }
}

// ---------------- elementwise add ----------------
__global__ void add_kernel(const float* __restrict__ a, const float* __restrict__ b,
                           float* __restrict__ c, int n) {
    int i = blockIdx.x * 256 + threadIdx.x;
    if (i < n) c[i] = a[i] + b[i];
}

// ---------------- bilinear 2x upsample ----------------
__global__ void up2x_kernel(const float* __restrict__ src, float* __restrict__ dst) {
    int idx = blockIdx.x * 256 + threadIdx.x;
    const int total = BB * NCLS * OHW;
    if (idx >= total) return;
    int ox = idx & 127;
    int r = idx >> 7;
    int oy = r & 127;
    r >>= 7;
    float sy = oy * 0.5f - 0.25f;
    float sx = ox * 0.5f - 0.25f;
    float fy = floorf(sy), fx = floorf(sx);
    float wy = sy - fy, wx = sx - fx;
    int y0 = (int)fy, x0 = (int)fx;
    int y0c = max(y0, 0), y1c = min(y0 + 1, 63);
    int x0c = max(x0, 0), x1c = min(x0 + 1, 63);
    const float* s = src + (size_t)r * HW;
    float v00 = s[y0c*64+x0c], v01 = s[y0c*64+x1c];
    float v10 = s[y1c*64+x0c], v11 = s[y1c*64+x1c];
    dst[idx] = (1.f-wy)*((1.f-wx)*v00 + wx*v01) + wy*((1.f-wx)*v10 + wx*v11);
}

// ---------------- orchestration ----------------
extern "C" void kernel_launch(void* const* d_in, const int* in_sizes, int n_in,
                              void* d_out, int out_size) {
    (void)in_sizes; (void)n_in; (void)out_size;
    const float* x    = (const float*)d_in[0];
    const float* wp1  = (const float*)d_in[1];
    const float* sp1  = (const float*)d_in[2];
    const float* bp1  = (const float*)d_in[3];
    const float* wc1  = (const float*)d_in[4];
    const float* sc1  = (const float*)d_in[5];
    const float* bc1  = (const float*)d_in[6];
    const float* pwb  = (const float*)d_in[7];
    const float* pbb  = (const float*)d_in[8];
    const float* pwc  = (const float*)d_in[9];
    const float* pbc  = (const float*)d_in[10];
    const float* pwd  = (const float*)d_in[11];
    const float* pbd  = (const float*)d_in[12];
    const float* alpha = (const float*)d_in[13];
    const float* beta  = (const float*)d_in[14];
    const float* wp2  = (const float*)d_in[15];
    const float* sp2  = (const float*)d_in[16];
    const float* bp2  = (const float*)d_in[17];
    const float* wc2  = (const float*)d_in[18];
    const float* sc2  = (const float*)d_in[19];
    const float* bc2  = (const float*)d_in[20];
    const float* wlog = (const float*)d_in[21];
    const float* blog = (const float*)d_in[22];
    const float* wp3  = (const float*)d_in[23];
    const float* bp3  = (const float*)d_in[24];
    const float* wc3  = (const float*)d_in[25];
    const float* bc3  = (const float*)d_in[26];
    float* out = (float*)d_out;

    uint32_t *wt1p, *wbc1, *wt2p, *wbc2, *xtf, *xsp, *pamtf, *camsp;
    uint32_t *fbsp, *fcsp, *fdsp, *attnsp, *fp0cs, *fc0cs, *fc0rsA, *fc0rsB, *wdrs, *wbcrs, *catsp;
    float *campart, *wbc128, *bbc, *fbc;
    float *featp0, *featc0, *fd, *attn;
    float *pam, *featp, *cam, *featc, *fusion, *pout, *cout_, *fout;
    cudaGetSymbolAddress((void**)&wt1p, g_wt1p);
    cudaGetSymbolAddress((void**)&wbc1, g_wbc1);
    cudaGetSymbolAddress((void**)&wt2p, g_wt2p);
    cudaGetSymbolAddress((void**)&wbc2, g_wbc2);
    cudaGetSymbolAddress((void**)&xtf, g_xtf);
    cudaGetSymbolAddress((void**)&xsp, g_xsp);
    cudaGetSymbolAddress((void**)&pamtf, g_pamtf);
    cudaGetSymbolAddress((void**)&camsp, g_camsp);
    cudaGetSymbolAddress((void**)&fbsp, g_fbsp);
    cudaGetSymbolAddress((void**)&fcsp, g_fcsp);
    cudaGetSymbolAddress((void**)&fdsp, g_fdsp);
    cudaGetSymbolAddress((void**)&attnsp, g_attnsp);
    cudaGetSymbolAddress((void**)&fp0cs, g_fp0cs);
    cudaGetSymbolAddress((void**)&fc0cs, g_fc0cs);
    cudaGetSymbolAddress((void**)&fc0rsA, g_fc0rsA);
    cudaGetSymbolAddress((void**)&fc0rsB, g_fc0rsB);
    cudaGetSymbolAddress((void**)&wdrs, g_wdrs);
    cudaGetSymbolAddress((void**)&wbcrs, g_wbcrs);
    cudaGetSymbolAddress((void**)&catsp, g_catsp);
    cudaGetSymbolAddress((void**)&campart, g_campart);
    cudaGetSymbolAddress((void**)&wbc128, g_wbc128);
    cudaGetSymbolAddress((void**)&bbc, g_bbc);
    cudaGetSymbolAddress((void**)&fbc, g_fbc);
    cudaGetSymbolAddress((void**)&featp0, g_featp0);
    cudaGetSymbolAddress((void**)&featc0, g_featc0);
    cudaGetSymbolAddress((void**)&fd, g_fd);
    cudaGetSymbolAddress((void**)&attn, g_attn);
    cudaGetSymbolAddress((void**)&pam, g_pam);
    cudaGetSymbolAddress((void**)&featp, g_featp);
    cudaGetSymbolAddress((void**)&cam, g_cam);
    cudaGetSymbolAddress((void**)&featc, g_featc);
    cudaGetSymbolAddress((void**)&fusion, g_fusion);
    cudaGetSymbolAddress((void**)&pout, g_pout);
    cudaGetSymbolAddress((void**)&cout_, g_cout);
    cudaGetSymbolAddress((void**)&fout, g_fout);

    cudaFuncSetAttribute(conv_tf32ca_kernel,
                         cudaFuncAttributeMaxDynamicSharedMemorySize, CONV_SMEM);
    cudaFuncSetAttribute(conv_bf16ca_kernel,
                         cudaFuncAttributeMaxDynamicSharedMemorySize, CONV_SMEM);
    cudaFuncSetAttribute(gemm_bf16s2_kernel<0, 0>,
                         cudaFuncAttributeMaxDynamicSharedMemorySize, GSMEM_BYTES);
    cudaFuncSetAttribute(gemm_bf16s2_kernel<1, 0>,
                         cudaFuncAttributeMaxDynamicSharedMemorySize, GSMEM_BYTES);
    cudaFuncSetAttribute(gemm_bf16s2_kernel<1, 0, 1>,
                         cudaFuncAttributeMaxDynamicSharedMemorySize, GSMEM_BYTES);
    cudaFuncSetAttribute(gemm_bf16s2_kernel<1, 1>,
                         cudaFuncAttributeMaxDynamicSharedMemorySize, GSMEM_BYTES);
    cudaFuncSetAttribute(gemm_bf16s2_kernel<1, 1, 1>,
                         cudaFuncAttributeMaxDynamicSharedMemorySize, GSMEM_BYTES);

    // c1 path first so conv_bf16ca is launch #4 (ncu capture slot)
    wsplitbf_kernel<<<8192, 256>>>(wc1, wbc1, CIN, IC);                               // 1
    packx_kernel<<<16384, 256>>>(x, xsp, xtf, 10, (size_t)BB << 22);                  // 2
    wtrans_kernel<<<4096, 256>>>(wp1, wt1p, CIN, IC);                                 // 3
    conv_bf16ca_kernel<<<dim3(128, 4), 256, CONV_SMEM>>>(xsp, wbc1, featc0, sc1, bc1, CIN, 1); // 4
    conv_tf32ca_kernel<<<dim3(128, 4), 256, CONV_SMEM>>>(xtf, wt1p, featp0, sp1, bp1, CIN, 1);
    wtrans_kernel<<<2048, 256>>>(wp2, wt2p, IC, IC);
    wsplitbf_kernel<<<2048, 256>>>(wc2, wbc2, IC, IC);

    // PAM projections, all tensor: fb+fc merged (M=128) and fd, both on fp0cs
    stackwbc_kernel<<<256, 256>>>(pwb, pwc, pbb, pbc, wbc128, bbc);
    packsp3_kernel<<<8192, 256>>>(featp0, fp0cs, 8, (size_t)BB << 20, 2);
    packrs3_kernel<<<128, 256>>>(wbc128, wbcrs, (size_t)128 << 8, 8, 1);
    packrs3_kernel<<<512, 256>>>(pwd, wdrs, (size_t)IC << 8, 8, 1);
    gemm_bf16s2_kernel<1, 0, 1><<<dim3(1, 32, 4), 128, GSMEM_BYTES>>>(
        wbcrs, 0, K2C2,
        fp0cs, (long)K2C2 * HW, HW,
        fbc, (long)128 * HW, HW, 0, bbc, 0, K2C2);
    gemm_bf16s2_kernel<1, 0, 1><<<dim3(4, 32, 4), 128, GSMEM_BYTES>>>(
        wdrs, 0, K2C2,
        fp0cs, (long)K2C2 * HW, HW,
        fd, (long)IC * HW, HW, 0, pbd, 0, K2C2);

    // PAM logits + fused softmax+pack
    packsp3_kernel<<<1024, 256>>>(fbc, fbsp, 5, (size_t)BB << 17, 1, 19);
    packsp3_kernel<<<1024, 256>>>(fbc + 64 * HW, fcsp, 5, (size_t)BB << 17, 2, 19);
    gemm_bf16s2_kernel<0, 0><<<dim3(32, 32, 4), 128, GSMEM_BYTES>>>(
        fbsp, (long)(3 * C8 / 2) * HW, HW,
        fcsp, (long)(3 * C8 / 2) * HW, HW,
        attn, (long)HW * HW, HW, 0, 0, 0, 3 * C8 / 2);
    softmax_pack_kernel<<<BB * HW, 256>>>(attn, attnsp);

    // PAM apply (SWAP)
    packrs3_kernel<<<8192, 256>>>(fd, fdsp, (size_t)(BB * IC) << 11, 11, 1);
    gemm_bf16s2_kernel<1, 1, 1><<<dim3(4, 32, 4), 128, GSMEM_BYTES>>>(
        fdsp, (long)IC * K2HW, K2HW,
        attnsp, (long)HW * K2HW, K2HW,
        pam, (long)IC * HW, HW, alpha, 0, featp0, K2HW);

    // conv p2
    packtf_kernel<<<8192, 256>>>(pam, pamtf, (size_t)BB * IC * HW);
    conv_tf32ca_kernel<<<dim3(128, 4), 256, CONV_SMEM>>>(pamtf, wt2p, featp, sp2, bp2, IC, 1);

    // CAM: gram split-K x4 + fused reduce/softmax/pack + apply (SWAP)
    packrs3_kernel<<<8192, 256>>>(featc0, fc0rsA, (size_t)(BB * IC) << 11, 11, 1);
    packrs3_kernel<<<8192, 256>>>(featc0, fc0rsB, (size_t)(BB * IC) << 11, 11, 2);
    gemm_bf16s2_kernel<1, 1><<<dim3(4, 4, 16), 128, GSMEM_BYTES>>>(
        fc0rsA, (long)IC * K2HW, K2HW,
        fc0rsB, (long)IC * K2HW, K2HW,
        campart, (long)IC * IC, IC, 0, 0, 0, K2HW / 4,
        4, (long)(K2HW / 4), (long)(K2HW / 4), (long)BB * IC * IC);
    cam_softmax_pack_kernel<<<BB * IC, 128>>>(campart, catsp, 4, (long)BB * IC * IC);
    packsp3_kernel<<<8192, 256>>>(featc0, fc0cs, 8, (size_t)BB << 20, 2);
    gemm_bf16s2_kernel<1, 0, 1><<<dim3(4, 32, 4), 128, GSMEM_BYTES>>>(
        catsp, (long)IC * K2C2, K2C2,
        fc0cs, (long)K2C2 * HW, HW,
        cam, (long)IC * HW, HW, beta, 0, featc0, K2C2);

    // conv c2
    packsp3_kernel<<<8192, 256>>>(cam, camsp, 8, (size_t)BB << 20, 2);
    conv_bf16ca_kernel<<<dim3(128, 4), 256, CONV_SMEM>>>(camsp, wbc2, featc, sc2, bc2, IC, 1);

    // fusion + heads
    add_kernel<<<(BB * IC * HW) / 256, 256>>>(featp, featc, fusion, BB * IC * HW);
    Head3 h;
    h.A[0] = wp3;  h.bias[0] = bp3;  h.B[0] = featp;  h.C[0] = pout;
    h.A[1] = wc3;  h.bias[1] = bc3;  h.B[1] = featc;  h.C[1] = cout_;
    h.A[2] = wlog; h.bias[2] = blog; h.B[2] = fusion; h.C[2] = fout;
    heads_kernel<<<dim3(32, 3, 4), 256>>>(h, IC);

    // upsample 2x into output
    const int outElems = BB * NCLS * OHW;
    up2x_kernel<<<(outElems + 255) / 256, 256>>>(pout, out);
    up2x_kernel<<<(outElems + 255) / 256, 256>>>(cout_, out + outElems);
    up2x_kernel<<<(outElems + 255) / 256, 256>>>(fout, out + 2 * (size_t)outElems);
}